// round 1
// baseline (speedup 1.0000x reference)
#include <cuda_runtime.h>
#include <mma.h>
#include <math.h>

using namespace nvcuda;

#define LSEQ 2048
#define HID  3072
#define NH   24
#define HD   128
#define MLPD 12288
#define W1N  21504   // 3*HID + MLP
#define CATN 15360   // HID + MLP
#define SLD  2056    // padded score-row stride (floats)

// ---------------- scratch (device globals; no allocations allowed) ----------
__device__ float g_mod[3 * HID];
__device__ float g_xmod[(size_t)LSEQ * HID];
__device__ float g_h[(size_t)LSEQ * W1N];
__device__ float g_q[(size_t)NH * LSEQ * HD];
__device__ float g_k[(size_t)NH * LSEQ * HD];
__device__ float g_v[(size_t)NH * LSEQ * HD];
__device__ float g_cat[(size_t)LSEQ * CATN];

// ---------------- 1) mod = silu(vec) @ mod_w + mod_b -----------------------
__global__ void k_mod_gemv(const float* __restrict__ vec,
                           const float* __restrict__ mw,
                           const float* __restrict__ mb) {
    __shared__ float sv[HID];
    int tid = threadIdx.x;
    for (int i = tid; i < HID; i += 256) {
        float v = vec[i];
        sv[i] = v / (1.f + expf(-v));
    }
    __syncthreads();
    int j = tid & 63, ky = tid >> 6;
    int col = blockIdx.x * 64 + j;
    const float* wp = mw + col;
    float acc = 0.f;
    int i0 = ky * 768;
#pragma unroll 4
    for (int i = i0; i < i0 + 768; ++i)
        acc += sv[i] * wp[(size_t)i * (3 * HID)];
    __shared__ float red[4][64];
    red[ky][j] = acc;
    __syncthreads();
    if (ky == 0)
        g_mod[col] = red[0][j] + red[1][j] + red[2][j] + red[3][j] + mb[col];
}

// ---------------- 2) LayerNorm + modulate -----------------------------------
__global__ void k_ln_mod(const float* __restrict__ x,
                         const float* __restrict__ gamma,
                         const float* __restrict__ beta) {
    int l = blockIdx.x;
    const float* xr = x + (size_t)l * HID;
    float s = 0.f, ss = 0.f;
    for (int c = threadIdx.x; c < HID; c += 256) {
        float v = xr[c];
        s += v; ss += v * v;
    }
    __shared__ float rs[8], rss[8];
    for (int o = 16; o > 0; o >>= 1) {
        s  += __shfl_xor_sync(~0u, s, o);
        ss += __shfl_xor_sync(~0u, ss, o);
    }
    int w = threadIdx.x >> 5;
    if ((threadIdx.x & 31) == 0) { rs[w] = s; rss[w] = ss; }
    __syncthreads();
    float S = 0.f, SS = 0.f;
#pragma unroll
    for (int i = 0; i < 8; ++i) { S += rs[i]; SS += rss[i]; }
    float mu   = S * (1.f / HID);
    float var  = SS * (1.f / HID) - mu * mu;
    float rstd = rsqrtf(var + 1e-6f);
    float* o = g_xmod + (size_t)l * HID;
    for (int c = threadIdx.x; c < HID; c += 256) {
        float ln = (xr[c] - mu) * rstd * gamma[c] + beta[c];
        o[c] = (1.f + g_mod[HID + c]) * ln + g_mod[c];
    }
}

// ---------------- TF32 GEMM: C[M,N] = A[M,K]@B[K,N] + bias (opt gated resid)
// block tile 128x128, BK=32, 8 warps (4 along M x 2 along N), warp 32x64.
__global__ void __launch_bounds__(256) k_gemm(
    const float* __restrict__ A, int lda,
    const float* __restrict__ B, int ldb,
    float* __restrict__ C, int ldc, int K,
    const float* __restrict__ bias,
    const float* __restrict__ gate,
    const float* __restrict__ resid) {
    __shared__ float As[128][36];
    __shared__ float Bs[32][132];
    __shared__ float stage[8][16][16];

    int tid = threadIdx.x;
    int m0 = blockIdx.x * 128, n0 = blockIdx.y * 128;
    int w = tid >> 5, lane = tid & 31;
    int wm = w & 3, wn = w >> 2;

    wmma::fragment<wmma::accumulator, 16, 16, 8, float> acc[2][4];
#pragma unroll
    for (int i = 0; i < 2; i++)
#pragma unroll
        for (int j = 0; j < 4; j++) wmma::fill_fragment(acc[i][j], 0.f);

    for (int k0 = 0; k0 < K; k0 += 32) {
#pragma unroll
        for (int f = tid; f < 1024; f += 256) {
            int r = f >> 3, c4 = (f & 7) * 4;
            float4 v = *reinterpret_cast<const float4*>(A + (size_t)(m0 + r) * lda + k0 + c4);
            As[r][c4 + 0] = wmma::__float_to_tf32(v.x);
            As[r][c4 + 1] = wmma::__float_to_tf32(v.y);
            As[r][c4 + 2] = wmma::__float_to_tf32(v.z);
            As[r][c4 + 3] = wmma::__float_to_tf32(v.w);
        }
#pragma unroll
        for (int f = tid; f < 1024; f += 256) {
            int r = f >> 5, c4 = (f & 31) * 4;
            float4 v = *reinterpret_cast<const float4*>(B + (size_t)(k0 + r) * ldb + n0 + c4);
            Bs[r][c4 + 0] = wmma::__float_to_tf32(v.x);
            Bs[r][c4 + 1] = wmma::__float_to_tf32(v.y);
            Bs[r][c4 + 2] = wmma::__float_to_tf32(v.z);
            Bs[r][c4 + 3] = wmma::__float_to_tf32(v.w);
        }
        __syncthreads();
#pragma unroll
        for (int kt = 0; kt < 4; ++kt) {
            int kk = kt * 8;
            wmma::fragment<wmma::matrix_a, 16, 16, 8, wmma::precision::tf32, wmma::row_major> a[2];
            wmma::fragment<wmma::matrix_b, 16, 16, 8, wmma::precision::tf32, wmma::row_major> b[4];
#pragma unroll
            for (int i = 0; i < 2; i++)
                wmma::load_matrix_sync(a[i], &As[wm * 32 + i * 16][kk], 36);
#pragma unroll
            for (int j = 0; j < 4; j++)
                wmma::load_matrix_sync(b[j], &Bs[kk][wn * 64 + j * 16], 132);
#pragma unroll
            for (int i = 0; i < 2; i++)
#pragma unroll
                for (int j = 0; j < 4; j++)
                    wmma::mma_sync(acc[i][j], a[i], b[j], acc[i][j]);
        }
        __syncthreads();
    }
    // epilogue
#pragma unroll
    for (int i = 0; i < 2; i++)
#pragma unroll
        for (int j = 0; j < 4; j++) {
            wmma::store_matrix_sync(&stage[w][0][0], acc[i][j], 16, wmma::mem_row_major);
            __syncwarp();
            for (int e = lane; e < 256; e += 32) {
                int r = e >> 4, c = e & 15;
                int gm = m0 + wm * 32 + i * 16 + r;
                int gn = n0 + wn * 64 + j * 16 + c;
                float val = stage[w][r][c] + bias[gn];
                if (gate) val = resid[(size_t)gm * ldc + gn] + gate[gn] * val;
                C[(size_t)gm * ldc + gn] = val;
            }
            __syncwarp();
        }
}

// ---------------- 3) q/k rmsnorm + rope, v copy; [H][L][D] layout -----------
__global__ void k_qkv(const float* __restrict__ pe,
                      const float* __restrict__ qs,
                      const float* __restrict__ ks) {
    int l = blockIdx.x, hh = blockIdx.y, d = threadIdx.x;
    const float* hrow = g_h + (size_t)l * W1N;
    float qv = hrow[hh * HD + d];
    float kv = hrow[HID + hh * HD + d];
    float vv = hrow[2 * HID + hh * HD + d];
    float sq = qv * qv, sk = kv * kv;
    for (int o = 16; o > 0; o >>= 1) {
        sq += __shfl_xor_sync(~0u, sq, o);
        sk += __shfl_xor_sync(~0u, sk, o);
    }
    __shared__ float wsq[4], wsk[4];
    int w = d >> 5;
    if ((d & 31) == 0) { wsq[w] = sq; wsk[w] = sk; }
    __syncthreads();
    float msq = (wsq[0] + wsq[1] + wsq[2] + wsq[3]) * (1.f / HD);
    float msk = (wsk[0] + wsk[1] + wsk[2] + wsk[3]) * (1.f / HD);
    __shared__ float nq[HD], nk[HD];
    nq[d] = qv * rsqrtf(msq + 1e-6f) * qs[d];
    nk[d] = kv * rsqrtf(msk + 1e-6f) * ks[d];
    __syncthreads();
    int c = d >> 1, r = d & 1;
    const float* pp = pe + ((size_t)l * 64 + c) * 4 + r * 2;
    float qr = pp[0] * nq[2 * c] + pp[1] * nq[2 * c + 1];
    float kr = pp[0] * nk[2 * c] + pp[1] * nk[2 * c + 1];
    size_t base = ((size_t)hh * LSEQ + l) * HD + d;
    g_q[base] = wmma::__float_to_tf32(qr * 0.08838834764831845f);  // * D^-0.5
    g_k[base] = wmma::__float_to_tf32(kr);
    g_v[base] = wmma::__float_to_tf32(vv);
}

// ---------------- 4) attention: block = (16 q rows, 1 head), exact softmax --
__global__ void __launch_bounds__(256) k_attn() {
    extern __shared__ float S[];                 // [16][SLD]
    __shared__ float Qs[16][132];
    __shared__ float Os[8][16][16];
    __shared__ float inv_l[16];
    int tid = threadIdx.x, w = tid >> 5, lane = tid & 31;
    int hh = blockIdx.y;
    int q0 = blockIdx.x * 16;
    const float* Qg = g_q + ((size_t)hh * LSEQ + q0) * HD;
    const float* Kg = g_k + (size_t)hh * LSEQ * HD;
    const float* Vg = g_v + (size_t)hh * LSEQ * HD;

    for (int f = tid; f < 16 * HD; f += 256) Qs[f >> 7][f & 127] = Qg[f];
    __syncthreads();

    // scores S[16][2048] = Q @ K^T
    for (int jt = w; jt < 128; jt += 8) {
        wmma::fragment<wmma::accumulator, 16, 16, 8, float> sacc;
        wmma::fill_fragment(sacc, 0.f);
#pragma unroll
        for (int kk = 0; kk < HD; kk += 8) {
            wmma::fragment<wmma::matrix_a, 16, 16, 8, wmma::precision::tf32, wmma::row_major> a;
            wmma::fragment<wmma::matrix_b, 16, 16, 8, wmma::precision::tf32, wmma::col_major> b;
            wmma::load_matrix_sync(a, &Qs[0][kk], 132);
            wmma::load_matrix_sync(b, Kg + (size_t)jt * 16 * HD + kk, HD);
            wmma::mma_sync(sacc, a, b, sacc);
        }
        wmma::store_matrix_sync(&S[jt * 16], sacc, SLD, wmma::mem_row_major);
    }
    __syncthreads();

    // exact softmax: warp w owns rows 2w, 2w+1
#pragma unroll
    for (int rr = 0; rr < 2; ++rr) {
        int row = w * 2 + rr;
        float* Sr = S + (size_t)row * SLD;
        float m = -1e30f;
        for (int i = lane; i < LSEQ; i += 32) m = fmaxf(m, Sr[i]);
        for (int o = 16; o > 0; o >>= 1) m = fmaxf(m, __shfl_xor_sync(~0u, m, o));
        float sum = 0.f;
        for (int i = lane; i < LSEQ; i += 32) {
            float e = __expf(Sr[i] - m);
            sum += e;
            Sr[i] = wmma::__float_to_tf32(e);
        }
        for (int o = 16; o > 0; o >>= 1) sum += __shfl_xor_sync(~0u, sum, o);
        if (lane == 0) inv_l[row] = 1.f / sum;
    }
    __syncthreads();

    // O = P @ V ; warp w owns output cols [w*16, w*16+16)
    wmma::fragment<wmma::accumulator, 16, 16, 8, float> oacc;
    wmma::fill_fragment(oacc, 0.f);
    for (int kk = 0; kk < LSEQ; kk += 8) {
        wmma::fragment<wmma::matrix_a, 16, 16, 8, wmma::precision::tf32, wmma::row_major> a;
        wmma::fragment<wmma::matrix_b, 16, 16, 8, wmma::precision::tf32, wmma::row_major> b;
        wmma::load_matrix_sync(a, &S[kk], SLD);
        wmma::load_matrix_sync(b, Vg + (size_t)kk * HD + w * 16, HD);
        wmma::mma_sync(oacc, a, b, oacc);
    }
    wmma::store_matrix_sync(&Os[w][0][0], oacc, 16, wmma::mem_row_major);
    __syncwarp();
    for (int e = lane; e < 256; e += 32) {
        int r = e >> 4, c = e & 15;
        float val = Os[w][r][c] * inv_l[r];
        g_cat[(size_t)(q0 + r) * CATN + hh * HD + w * 16 + c] = wmma::__float_to_tf32(val);
    }
}

// ---------------- 5) gelu(mlp) into concat buffer ---------------------------
__global__ void k_gelu() {
    size_t total = (size_t)LSEQ * MLPD;
    for (size_t idx = (size_t)blockIdx.x * 256 + threadIdx.x; idx < total;
         idx += (size_t)gridDim.x * 256) {
        size_t l = idx / MLPD, j = idx % MLPD;
        float v = g_h[l * W1N + 3 * HID + j];
        float t = 0.7978845608028654f * (v + 0.044715f * v * v * v);
        float g = 0.5f * v * (1.f + tanhf(t));
        g_cat[l * CATN + HID + j] = wmma::__float_to_tf32(g);
    }
}

// ---------------- launch ----------------------------------------------------
extern "C" void kernel_launch(void* const* d_in, const int* in_sizes, int n_in,
                              void* d_out, int out_size) {
    const float* x     = (const float*)d_in[0];
    const float* vec   = (const float*)d_in[1];
    const float* pe    = (const float*)d_in[2];
    const float* mod_w = (const float*)d_in[3];
    const float* mod_b = (const float*)d_in[4];
    const float* ln_g  = (const float*)d_in[5];
    const float* ln_b  = (const float*)d_in[6];
    const float* w1    = (const float*)d_in[7];
    const float* b1    = (const float*)d_in[8];
    const float* q_s   = (const float*)d_in[9];
    const float* k_s   = (const float*)d_in[10];
    const float* w2    = (const float*)d_in[11];
    const float* b2    = (const float*)d_in[12];
    float* out = (float*)d_out;

    float *p_xmod, *p_h, *p_cat, *p_mod;
    cudaGetSymbolAddress((void**)&p_xmod, g_xmod);
    cudaGetSymbolAddress((void**)&p_h,    g_h);
    cudaGetSymbolAddress((void**)&p_cat,  g_cat);
    cudaGetSymbolAddress((void**)&p_mod,  g_mod);

    cudaFuncSetAttribute(k_attn, cudaFuncAttributeMaxDynamicSharedMemorySize,
                         16 * SLD * 4);

    k_mod_gemv<<<144, 256>>>(vec, mod_w, mod_b);
    k_ln_mod<<<LSEQ, 256>>>(x, ln_g, ln_b);
    // h = x_mod @ w1 + b1
    k_gemm<<<dim3(16, 168), 256>>>(p_xmod, HID, w1, W1N, p_h, W1N, HID,
                                   b1, nullptr, nullptr);
    k_qkv<<<dim3(LSEQ, NH), 128>>>(pe, q_s, k_s);
    k_attn<<<dim3(128, NH), 256, 16 * SLD * 4>>>();
    k_gelu<<<12288, 256>>>();
    // out = x + gate * (cat @ w2 + b2)
    k_gemm<<<dim3(16, 24), 256>>>(p_cat, CATN, w2, HID, out, HID, CATN,
                                  b2, p_mod + 2 * HID, x);
    (void)in_sizes; (void)n_in; (void)out_size;
}

// round 4
// speedup vs baseline: 1.0939x; 1.0939x over previous
#include <cuda_runtime.h>
#include <cstdint>
#include <stdint.h>
#include <mma.h>
#include <math.h>

using namespace nvcuda;

#define LSEQ 2048
#define HID  3072
#define NH   24
#define HD   128
#define MLPD 12288
#define W1N  21504   // 3*HID + MLP
#define CATN 15360   // HID + MLP
#define SLD  2056    // padded score-row stride (floats)

// ---------------- scratch (device globals; no allocations allowed) ----------
__device__ float g_mod[3 * HID];
__device__ float g_xmod[(size_t)LSEQ * HID];
__device__ float g_h[(size_t)LSEQ * W1N];
__device__ float g_q[(size_t)NH * LSEQ * HD];
__device__ float g_k[(size_t)NH * LSEQ * HD];
__device__ float g_v[(size_t)NH * LSEQ * HD];
__device__ float g_cat[(size_t)LSEQ * CATN];
__device__ float g_w1t[(size_t)HID * W1N];
__device__ float g_w2t[(size_t)CATN * HID];

// ---------------- cp.async helpers ------------------------------------------
__device__ __forceinline__ void cp16(unsigned dst, const void* src) {
    asm volatile("cp.async.cg.shared.global [%0], [%1], 16;\n" :: "r"(dst), "l"(src));
}
__device__ __forceinline__ void cp_commit() {
    asm volatile("cp.async.commit_group;\n");
}
__device__ __forceinline__ void cp_wait0() {
    asm volatile("cp.async.wait_group 0;\n");
}
__device__ __forceinline__ void cp_wait1() {
    asm volatile("cp.async.wait_group 1;\n");
}
__device__ __forceinline__ unsigned saddr(const void* p) {
    return (unsigned)__cvta_generic_to_shared(p);
}

// ---------------- 0) tf32 round of weights ----------------------------------
__global__ void k_convert(const float* __restrict__ in, float* __restrict__ out,
                          size_t n4) {
    for (size_t i = (size_t)blockIdx.x * 256 + threadIdx.x; i < n4;
         i += (size_t)gridDim.x * 256) {
        float4 v = reinterpret_cast<const float4*>(in)[i];
        v.x = wmma::__float_to_tf32(v.x);
        v.y = wmma::__float_to_tf32(v.y);
        v.z = wmma::__float_to_tf32(v.z);
        v.w = wmma::__float_to_tf32(v.w);
        reinterpret_cast<float4*>(out)[i] = v;
    }
}

// ---------------- 1) mod = silu(vec) @ mod_w + mod_b ------------------------
__global__ void k_mod_gemv(const float* __restrict__ vec,
                           const float* __restrict__ mw,
                           const float* __restrict__ mb) {
    __shared__ float sv[HID];
    int tid = threadIdx.x;
    for (int i = tid; i < HID; i += 256) {
        float v = vec[i];
        sv[i] = v / (1.f + expf(-v));
    }
    __syncthreads();
    int j = tid & 63, ky = tid >> 6;
    int col = blockIdx.x * 64 + j;
    const float* wp = mw + col;
    float acc = 0.f;
    int i0 = ky * 768;
#pragma unroll 4
    for (int i = i0; i < i0 + 768; ++i)
        acc += sv[i] * wp[(size_t)i * (3 * HID)];
    __shared__ float red[4][64];
    red[ky][j] = acc;
    __syncthreads();
    if (ky == 0)
        g_mod[col] = red[0][j] + red[1][j] + red[2][j] + red[3][j] + mb[col];
}

// ---------------- 2) LayerNorm + modulate (writes tf32-rounded) --------------
__global__ void k_ln_mod(const float* __restrict__ x,
                         const float* __restrict__ gamma,
                         const float* __restrict__ beta) {
    int l = blockIdx.x;
    const float* xr = x + (size_t)l * HID;
    float s = 0.f, ss = 0.f;
    for (int c = threadIdx.x; c < HID; c += 256) {
        float v = xr[c];
        s += v; ss += v * v;
    }
    __shared__ float rs[8], rss[8];
    for (int o = 16; o > 0; o >>= 1) {
        s  += __shfl_xor_sync(~0u, s, o);
        ss += __shfl_xor_sync(~0u, ss, o);
    }
    int w = threadIdx.x >> 5;
    if ((threadIdx.x & 31) == 0) { rs[w] = s; rss[w] = ss; }
    __syncthreads();
    float S = 0.f, SS = 0.f;
#pragma unroll
    for (int i = 0; i < 8; ++i) { S += rs[i]; SS += rss[i]; }
    float mu   = S * (1.f / HID);
    float var  = SS * (1.f / HID) - mu * mu;
    float rstd = rsqrtf(var + 1e-6f);
    float* o = g_xmod + (size_t)l * HID;
    for (int c = threadIdx.x; c < HID; c += 256) {
        float ln = (xr[c] - mu) * rstd * gamma[c] + beta[c];
        o[c] = wmma::__float_to_tf32((1.f + g_mod[HID + c]) * ln + g_mod[c]);
    }
}

// ---------------- TF32 GEMM, cp.async double-buffered ------------------------
// C[M,N] = A[M,K]@B[K,N] + bias (optional gated residual).
// block tile 128x128, BK=32, 8 warps (4 along M x 2 along N), warp 32x64.
// A and B must already be tf32-rounded.
#define AS_STRIDE 36
#define BS_STRIDE 132
#define GEMM_DSMEM (2 * (128 * AS_STRIDE + 32 * BS_STRIDE) * 4)

__global__ void __launch_bounds__(256) k_gemm(
    const float* __restrict__ A, int lda,
    const float* __restrict__ B, int ldb,
    float* __restrict__ C, int ldc, int K,
    const float* __restrict__ bias,
    const float* __restrict__ gate,
    const float* __restrict__ resid) {
    extern __shared__ float dsm[];
    float* As0 = dsm;                              // [128][36]
    float* As1 = As0 + 128 * AS_STRIDE;
    float* Bs0 = As1 + 128 * AS_STRIDE;            // [32][132]
    float* Bs1 = Bs0 + 32 * BS_STRIDE;
    float* Asb[2] = {As0, As1};
    float* Bsb[2] = {Bs0, Bs1};
    __shared__ float stage[8][16][16];

    int tid = threadIdx.x;
    int m0 = blockIdx.x * 128, n0 = blockIdx.y * 128;
    int w = tid >> 5, lane = tid & 31;
    int wm = w & 3, wn = w >> 2;

    // per-thread copy slots
    int ar = tid >> 1, ac = (tid & 1) * 8;   // A: row 0..127, col base 0/8
    int br = tid >> 3, bc = (tid & 7) * 4;   // B: row 0..31,  col base *4

    wmma::fragment<wmma::accumulator, 16, 16, 8, float> acc[2][4];
#pragma unroll
    for (int i = 0; i < 2; i++)
#pragma unroll
        for (int j = 0; j < 4; j++) wmma::fill_fragment(acc[i][j], 0.f);

    int nsteps = K / 32;
    auto issue = [&](int s) {
        int k0 = s * 32;
        float* As = Asb[s & 1];
        float* Bs = Bsb[s & 1];
        // A: row ar, cols [ac,ac+8) and [ac+16,ac+24)  (four 16B chunks)
        {
            const float* src = A + (size_t)(m0 + ar) * lda + k0 + ac;
            unsigned dst = saddr(As + ar * AS_STRIDE + ac);
            cp16(dst, src);
            cp16(dst + 16, src + 4);
            cp16(dst + 64, src + 16);
            cp16(dst + 80, src + 20);
        }
        // B: row br, cols {bc, bc+32, bc+64, bc+96}
#pragma unroll
        for (int p = 0; p < 4; ++p) {
            int c = bc + p * 32;
            const float* src = B + (size_t)(k0 + br) * ldb + n0 + c;
            cp16(saddr(Bs + br * BS_STRIDE + c), src);
        }
    };

    issue(0);
    cp_commit();
    for (int s = 0; s < nsteps; ++s) {
        if (s + 1 < nsteps) {
            issue(s + 1);
            cp_commit();
            cp_wait1();
        } else {
            cp_wait0();
        }
        __syncthreads();
        float* As = Asb[s & 1];
        float* Bs = Bsb[s & 1];
#pragma unroll
        for (int kt = 0; kt < 4; ++kt) {
            int kk = kt * 8;
            wmma::fragment<wmma::matrix_a, 16, 16, 8, wmma::precision::tf32, wmma::row_major> a[2];
            wmma::fragment<wmma::matrix_b, 16, 16, 8, wmma::precision::tf32, wmma::row_major> b[4];
#pragma unroll
            for (int i = 0; i < 2; i++)
                wmma::load_matrix_sync(a[i], As + (wm * 32 + i * 16) * AS_STRIDE + kk, AS_STRIDE);
#pragma unroll
            for (int j = 0; j < 4; j++)
                wmma::load_matrix_sync(b[j], Bs + kk * BS_STRIDE + wn * 64 + j * 16, BS_STRIDE);
#pragma unroll
            for (int i = 0; i < 2; i++)
#pragma unroll
                for (int j = 0; j < 4; j++)
                    wmma::mma_sync(acc[i][j], a[i], b[j], acc[i][j]);
        }
        __syncthreads();
    }
    // epilogue
#pragma unroll
    for (int i = 0; i < 2; i++)
#pragma unroll
        for (int j = 0; j < 4; j++) {
            wmma::store_matrix_sync(&stage[w][0][0], acc[i][j], 16, wmma::mem_row_major);
            __syncwarp();
            for (int e = lane; e < 256; e += 32) {
                int r = e >> 4, c = e & 15;
                int gm = m0 + wm * 32 + i * 16 + r;
                int gn = n0 + wn * 64 + j * 16 + c;
                float val = stage[w][r][c] + bias[gn];
                if (gate) val = resid[(size_t)gm * ldc + gn] + gate[gn] * val;
                C[(size_t)gm * ldc + gn] = val;
            }
            __syncwarp();
        }
}

// ---------------- 3) q/k rmsnorm + rope, v copy; [H][L][D] layout ------------
__global__ void k_qkv(const float* __restrict__ pe,
                      const float* __restrict__ qs,
                      const float* __restrict__ ks) {
    int l = blockIdx.x, hh = blockIdx.y, d = threadIdx.x;
    const float* hrow = g_h + (size_t)l * W1N;
    float qv = hrow[hh * HD + d];
    float kv = hrow[HID + hh * HD + d];
    float vv = hrow[2 * HID + hh * HD + d];
    float sq = qv * qv, sk = kv * kv;
    for (int o = 16; o > 0; o >>= 1) {
        sq += __shfl_xor_sync(~0u, sq, o);
        sk += __shfl_xor_sync(~0u, sk, o);
    }
    __shared__ float wsq[4], wsk[4];
    int w = d >> 5;
    if ((d & 31) == 0) { wsq[w] = sq; wsk[w] = sk; }
    __syncthreads();
    float msq = (wsq[0] + wsq[1] + wsq[2] + wsq[3]) * (1.f / HD);
    float msk = (wsk[0] + wsk[1] + wsk[2] + wsk[3]) * (1.f / HD);
    __shared__ float nq[HD], nk[HD];
    nq[d] = qv * rsqrtf(msq + 1e-6f) * qs[d];
    nk[d] = kv * rsqrtf(msk + 1e-6f) * ks[d];
    __syncthreads();
    int c = d >> 1, r = d & 1;
    const float* pp = pe + ((size_t)l * 64 + c) * 4 + r * 2;
    float qr = pp[0] * nq[2 * c] + pp[1] * nq[2 * c + 1];
    float kr = pp[0] * nk[2 * c] + pp[1] * nk[2 * c + 1];
    size_t base = ((size_t)hh * LSEQ + l) * HD + d;
    g_q[base] = wmma::__float_to_tf32(qr * 0.08838834764831845f);  // * D^-0.5
    g_k[base] = wmma::__float_to_tf32(kr);
    g_v[base] = wmma::__float_to_tf32(vv);
}

// ---------------- 4) attention: block = (16 q rows, 1 head), exact softmax ---
// dyn smem: S[16][SLD] | Qs[16][132] | KVs[128][132]
#define QS_STRIDE 132
#define KV_STRIDE 132
#define ATTN_DSMEM ((16 * SLD + 16 * QS_STRIDE + 128 * KV_STRIDE) * 4)

__global__ void __launch_bounds__(256) k_attn() {
    extern __shared__ float dsm[];
    float* S   = dsm;
    float* Qs  = S + 16 * SLD;
    float* KVs = Qs + 16 * QS_STRIDE;
    __shared__ float Os[8][16][16];
    __shared__ float inv_l[16];

    int tid = threadIdx.x, w = tid >> 5, lane = tid & 31;
    int hh = blockIdx.y;
    int q0 = blockIdx.x * 16;
    const float* Qg = g_q + ((size_t)hh * LSEQ + q0) * HD;
    const float* Kg = g_k + (size_t)hh * LSEQ * HD;
    const float* Vg = g_v + (size_t)hh * LSEQ * HD;

    // load Q tile (16x128) via cp.async
    if (tid < 128) {
        int r = tid >> 3, c4 = (tid & 7) * 16;
        const float* src = Qg + r * HD + c4;
        unsigned dst = saddr(Qs + r * QS_STRIDE + c4);
        cp16(dst, src);
        cp16(dst + 16, src + 4);
        cp16(dst + 32, src + 8);
        cp16(dst + 48, src + 12);
    }
    cp_commit();
    cp_wait0();
    __syncthreads();

    // copy slot: 2 threads per row, each thread covers 64 floats (16 x 16B)
    int cr = tid >> 1, cc = (tid & 1) * 64;

    // phase 1: scores S[16][2048] = Q @ K^T, staging K 128 rows at a time
    for (int t = 0; t < 16; ++t) {
        {
            const float* src = Kg + (size_t)(t * 128 + cr) * HD + cc;
            unsigned dst = saddr(KVs + cr * KV_STRIDE + cc);
#pragma unroll
            for (int p = 0; p < 16; ++p) cp16(dst + p * 16, src + p * 4);
        }
        cp_commit();
        cp_wait0();
        __syncthreads();
        wmma::fragment<wmma::accumulator, 16, 16, 8, float> sacc;
        wmma::fill_fragment(sacc, 0.f);
#pragma unroll
        for (int kk = 0; kk < HD; kk += 8) {
            wmma::fragment<wmma::matrix_a, 16, 16, 8, wmma::precision::tf32, wmma::row_major> a;
            wmma::fragment<wmma::matrix_b, 16, 16, 8, wmma::precision::tf32, wmma::col_major> b;
            wmma::load_matrix_sync(a, Qs + kk, QS_STRIDE);
            wmma::load_matrix_sync(b, KVs + (w * 16) * KV_STRIDE + kk, KV_STRIDE);
            wmma::mma_sync(sacc, a, b, sacc);
        }
        wmma::store_matrix_sync(S + t * 128 + w * 16, sacc, SLD, wmma::mem_row_major);
        __syncthreads();
    }

    // phase 2: exact softmax, warp w owns rows 2w, 2w+1
#pragma unroll
    for (int rr = 0; rr < 2; ++rr) {
        int row = w * 2 + rr;
        float* Sr = S + (size_t)row * SLD;
        float m = -1e30f;
        for (int i = lane; i < LSEQ; i += 32) m = fmaxf(m, Sr[i]);
        for (int o = 16; o > 0; o >>= 1) m = fmaxf(m, __shfl_xor_sync(~0u, m, o));
        float sum = 0.f;
        for (int i = lane; i < LSEQ; i += 32) {
            float e = __expf(Sr[i] - m);
            sum += e;
            Sr[i] = wmma::__float_to_tf32(e);
        }
        for (int o = 16; o > 0; o >>= 1) sum += __shfl_xor_sync(~0u, sum, o);
        if (lane == 0) inv_l[row] = 1.f / sum;
    }
    __syncthreads();

    // phase 3: O = P @ V, staging V 128 rows at a time; warp w owns cols w*16..+16
    wmma::fragment<wmma::accumulator, 16, 16, 8, float> oacc;
    wmma::fill_fragment(oacc, 0.f);
    for (int t = 0; t < 16; ++t) {
        {
            const float* src = Vg + (size_t)(t * 128 + cr) * HD + cc;
            unsigned dst = saddr(KVs + cr * KV_STRIDE + cc);
#pragma unroll
            for (int p = 0; p < 16; ++p) cp16(dst + p * 16, src + p * 4);
        }
        cp_commit();
        cp_wait0();
        __syncthreads();
#pragma unroll
        for (int kk = 0; kk < 128; kk += 8) {
            wmma::fragment<wmma::matrix_a, 16, 16, 8, wmma::precision::tf32, wmma::row_major> a;
            wmma::fragment<wmma::matrix_b, 16, 16, 8, wmma::precision::tf32, wmma::row_major> b;
            wmma::load_matrix_sync(a, S + t * 128 + kk, SLD);
            wmma::load_matrix_sync(b, KVs + kk * KV_STRIDE + w * 16, KV_STRIDE);
            wmma::mma_sync(oacc, a, b, oacc);
        }
        __syncthreads();
    }
    wmma::store_matrix_sync(&Os[w][0][0], oacc, 16, wmma::mem_row_major);
    __syncwarp();
    for (int e = lane; e < 256; e += 32) {
        int r = e >> 4, c = e & 15;
        float val = Os[w][r][c] * inv_l[r];
        g_cat[(size_t)(q0 + r) * CATN + hh * HD + w * 16 + c] = wmma::__float_to_tf32(val);
    }
}

// ---------------- 5) gelu(mlp) into concat buffer (tf32-rounded) -------------
__global__ void k_gelu() {
    size_t total = (size_t)LSEQ * MLPD;
    for (size_t idx = (size_t)blockIdx.x * 256 + threadIdx.x; idx < total;
         idx += (size_t)gridDim.x * 256) {
        size_t l = idx / MLPD, j = idx % MLPD;
        float v = g_h[l * W1N + 3 * HID + j];
        float t = 0.7978845608028654f * (v + 0.044715f * v * v * v);
        float g = 0.5f * v * (1.f + tanhf(t));
        g_cat[l * CATN + HID + j] = wmma::__float_to_tf32(g);
    }
}

// ---------------- launch -----------------------------------------------------
extern "C" void kernel_launch(void* const* d_in, const int* in_sizes, int n_in,
                              void* d_out, int out_size) {
    const float* x     = (const float*)d_in[0];
    const float* vec   = (const float*)d_in[1];
    const float* pe    = (const float*)d_in[2];
    const float* mod_w = (const float*)d_in[3];
    const float* mod_b = (const float*)d_in[4];
    const float* ln_g  = (const float*)d_in[5];
    const float* ln_b  = (const float*)d_in[6];
    const float* w1    = (const float*)d_in[7];
    const float* b1    = (const float*)d_in[8];
    const float* q_s   = (const float*)d_in[9];
    const float* k_s   = (const float*)d_in[10];
    const float* w2    = (const float*)d_in[11];
    const float* b2    = (const float*)d_in[12];
    float* out = (float*)d_out;

    float *p_xmod, *p_h, *p_cat, *p_mod, *p_w1t, *p_w2t;
    cudaGetSymbolAddress((void**)&p_xmod, g_xmod);
    cudaGetSymbolAddress((void**)&p_h,    g_h);
    cudaGetSymbolAddress((void**)&p_cat,  g_cat);
    cudaGetSymbolAddress((void**)&p_mod,  g_mod);
    cudaGetSymbolAddress((void**)&p_w1t,  g_w1t);
    cudaGetSymbolAddress((void**)&p_w2t,  g_w2t);

    cudaFuncSetAttribute(k_attn, cudaFuncAttributeMaxDynamicSharedMemorySize,
                         ATTN_DSMEM);
    cudaFuncSetAttribute(k_gemm, cudaFuncAttributeMaxDynamicSharedMemorySize,
                         GEMM_DSMEM);

    k_convert<<<4096, 256>>>(w1, p_w1t, (size_t)HID * W1N / 4);
    k_convert<<<4096, 256>>>(w2, p_w2t, (size_t)CATN * HID / 4);
    k_mod_gemv<<<144, 256>>>(vec, mod_w, mod_b);
    k_ln_mod<<<LSEQ, 256>>>(x, ln_g, ln_b);
    // h = x_mod @ w1 + b1
    k_gemm<<<dim3(16, 168), 256, GEMM_DSMEM>>>(p_xmod, HID, p_w1t, W1N, p_h,
                                               W1N, HID, b1, nullptr, nullptr);
    k_qkv<<<dim3(LSEQ, NH), 128>>>(pe, q_s, k_s);
    k_attn<<<dim3(128, NH), 256, ATTN_DSMEM>>>();
    k_gelu<<<12288, 256>>>();
    // out = x + gate * (cat @ w2 + b2)
    k_gemm<<<dim3(16, 24), 256, GEMM_DSMEM>>>(p_cat, CATN, p_w2t, HID, out,
                                              HID, CATN, b2, p_mod + 2 * HID, x);
    (void)in_sizes; (void)n_in; (void)out_size;
}

// round 6
// speedup vs baseline: 2.7315x; 2.4971x over previous
#include <cuda_runtime.h>
#include <cstdint>
#include <stdint.h>
#include <cuda_fp16.h>
#include <mma.h>
#include <math.h>

using namespace nvcuda;

#define LSEQ 2048
#define HID  3072
#define NH   24
#define HD   128
#define MLPD 12288
#define W1N  21504   // 3*HID + MLP
#define CATN 15360   // HID + MLP
#define SLD  2056    // padded score-row stride (floats)

// ---------------- scratch (device globals; no allocations allowed) ----------
__device__ float  g_mod[3 * HID];
__device__ __half g_xmod[(size_t)LSEQ * HID];
__device__ float  g_h[(size_t)LSEQ * W1N];
__device__ __half g_q[(size_t)NH * LSEQ * HD];
__device__ __half g_k[(size_t)NH * LSEQ * HD];
__device__ __half g_v[(size_t)NH * LSEQ * HD];
__device__ __half g_cat[(size_t)LSEQ * CATN];
__device__ __half g_w1h[(size_t)HID * W1N];
__device__ __half g_w2h[(size_t)CATN * HID];

// ---------------- cp.async helpers ------------------------------------------
__device__ __forceinline__ void cp16(unsigned dst, const void* src) {
    asm volatile("cp.async.cg.shared.global [%0], [%1], 16;\n" :: "r"(dst), "l"(src));
}
__device__ __forceinline__ void cp_commit() {
    asm volatile("cp.async.commit_group;\n");
}
__device__ __forceinline__ void cp_wait0() {
    asm volatile("cp.async.wait_group 0;\n");
}
__device__ __forceinline__ void cp_wait1() {
    asm volatile("cp.async.wait_group 1;\n");
}
__device__ __forceinline__ unsigned saddr(const void* p) {
    return (unsigned)__cvta_generic_to_shared(p);
}

// ---------------- 0) fp32 -> fp16 weight conversion --------------------------
__global__ void k_convert_h(const float* __restrict__ in, __half* __restrict__ out,
                            size_t n8) {
    const float4* in4 = reinterpret_cast<const float4*>(in);
    uint4* out4 = reinterpret_cast<uint4*>(out);
    for (size_t i = (size_t)blockIdx.x * 256 + threadIdx.x; i < n8;
         i += (size_t)gridDim.x * 256) {
        float4 a = in4[2 * i], b = in4[2 * i + 1];
        __half2 h0 = __floats2half2_rn(a.x, a.y);
        __half2 h1 = __floats2half2_rn(a.z, a.w);
        __half2 h2 = __floats2half2_rn(b.x, b.y);
        __half2 h3 = __floats2half2_rn(b.z, b.w);
        uint4 o;
        o.x = *reinterpret_cast<unsigned*>(&h0);
        o.y = *reinterpret_cast<unsigned*>(&h1);
        o.z = *reinterpret_cast<unsigned*>(&h2);
        o.w = *reinterpret_cast<unsigned*>(&h3);
        out4[i] = o;
    }
}

// ---------------- nop (shifts ncu -s 5 onto GEMM1) ---------------------------
__global__ void k_nop() {}

// ---------------- 1) mod = silu(vec) @ mod_w + mod_b ------------------------
__global__ void k_mod_gemv(const float* __restrict__ vec,
                           const float* __restrict__ mw,
                           const float* __restrict__ mb) {
    __shared__ float sv[HID];
    int tid = threadIdx.x;
    for (int i = tid; i < HID; i += 256) {
        float v = vec[i];
        sv[i] = v / (1.f + expf(-v));
    }
    __syncthreads();
    int j = tid & 63, ky = tid >> 6;
    int col = blockIdx.x * 64 + j;
    const float* wp = mw + col;
    float acc = 0.f;
    int i0 = ky * 768;
#pragma unroll 4
    for (int i = i0; i < i0 + 768; ++i)
        acc += sv[i] * wp[(size_t)i * (3 * HID)];
    __shared__ float red[4][64];
    red[ky][j] = acc;
    __syncthreads();
    if (ky == 0)
        g_mod[col] = red[0][j] + red[1][j] + red[2][j] + red[3][j] + mb[col];
}

// ---------------- 2) LayerNorm + modulate (writes fp16) ----------------------
__global__ void k_ln_mod(const float* __restrict__ x,
                         const float* __restrict__ gamma,
                         const float* __restrict__ beta) {
    int l = blockIdx.x;
    const float* xr = x + (size_t)l * HID;
    float s = 0.f, ss = 0.f;
    for (int c = threadIdx.x; c < HID; c += 256) {
        float v = xr[c];
        s += v; ss += v * v;
    }
    __shared__ float rs[8], rss[8];
    for (int o = 16; o > 0; o >>= 1) {
        s  += __shfl_xor_sync(~0u, s, o);
        ss += __shfl_xor_sync(~0u, ss, o);
    }
    int w = threadIdx.x >> 5;
    if ((threadIdx.x & 31) == 0) { rs[w] = s; rss[w] = ss; }
    __syncthreads();
    float S = 0.f, SS = 0.f;
#pragma unroll
    for (int i = 0; i < 8; ++i) { S += rs[i]; SS += rss[i]; }
    float mu   = S * (1.f / HID);
    float var  = SS * (1.f / HID) - mu * mu;
    float rstd = rsqrtf(var + 1e-6f);
    __half* o = g_xmod + (size_t)l * HID;
    for (int c = threadIdx.x; c < HID; c += 256) {
        float ln = (xr[c] - mu) * rstd * gamma[c] + beta[c];
        o[c] = __float2half_rn((1.f + g_mod[HID + c]) * ln + g_mod[c]);
    }
}

// ---------------- FP16 GEMM, cp.async double-buffered ------------------------
// C[M,N] = A[M,K]@B[K,N] + bias (optional gated residual). fp32 accumulate.
// block tile 128x128, BK=32, 8 warps (4 along M x 2 along N), warp 32x64.
#define AS_H 40    // half stride for A tile rows
#define BS_H 136   // half stride for B tile rows
#define GEMM_DSMEM (2 * (128 * AS_H + 32 * BS_H) * 2)

__global__ void __launch_bounds__(256) k_gemm(
    const __half* __restrict__ A, int lda,
    const __half* __restrict__ B, int ldb,
    float* __restrict__ C, int ldc, int K,
    const float* __restrict__ bias,
    const float* __restrict__ gate,
    const float* __restrict__ resid) {
    extern __shared__ __half hsm[];
    __half* As0 = hsm;                      // [128][AS_H]
    __half* As1 = As0 + 128 * AS_H;
    __half* Bs0 = As1 + 128 * AS_H;         // [32][BS_H]
    __half* Bs1 = Bs0 + 32 * BS_H;
    __half* Asb[2] = {As0, As1};
    __half* Bsb[2] = {Bs0, Bs1};
    __shared__ float stage[8][16][16];

    int tid = threadIdx.x;
    int m0 = blockIdx.x * 128, n0 = blockIdx.y * 128;
    int w = tid >> 5, lane = tid & 31;
    int wm = w & 3, wn = w >> 2;

    // per-thread copy slots (halves)
    int ar = tid >> 1, ac = (tid & 1) * 16;  // A: row 0..127, 16 halves
    int br = tid >> 3, bc = (tid & 7) * 16;  // B: row 0..31, 16 halves

    wmma::fragment<wmma::accumulator, 16, 16, 16, float> acc[2][4];
#pragma unroll
    for (int i = 0; i < 2; i++)
#pragma unroll
        for (int j = 0; j < 4; j++) wmma::fill_fragment(acc[i][j], 0.f);

    int nsteps = K / 32;
    auto issue = [&](int s) {
        int k0 = s * 32;
        __half* As = Asb[s & 1];
        __half* Bs = Bsb[s & 1];
        {
            const __half* src = A + (size_t)(m0 + ar) * lda + k0 + ac;
            unsigned dst = saddr(As + ar * AS_H + ac);
            cp16(dst, src);
            cp16(dst + 16, src + 8);
        }
        {
            const __half* src = B + (size_t)(k0 + br) * ldb + n0 + bc;
            unsigned dst = saddr(Bs + br * BS_H + bc);
            cp16(dst, src);
            cp16(dst + 16, src + 8);
        }
    };

    issue(0);
    cp_commit();
    for (int s = 0; s < nsteps; ++s) {
        if (s + 1 < nsteps) {
            issue(s + 1);
            cp_commit();
            cp_wait1();
        } else {
            cp_wait0();
        }
        __syncthreads();
        __half* As = Asb[s & 1];
        __half* Bs = Bsb[s & 1];
#pragma unroll
        for (int kt = 0; kt < 2; ++kt) {
            int kk = kt * 16;
            wmma::fragment<wmma::matrix_a, 16, 16, 16, __half, wmma::row_major> a[2];
            wmma::fragment<wmma::matrix_b, 16, 16, 16, __half, wmma::row_major> b[4];
#pragma unroll
            for (int i = 0; i < 2; i++)
                wmma::load_matrix_sync(a[i], As + (wm * 32 + i * 16) * AS_H + kk, AS_H);
#pragma unroll
            for (int j = 0; j < 4; j++)
                wmma::load_matrix_sync(b[j], Bs + kk * BS_H + wn * 64 + j * 16, BS_H);
#pragma unroll
            for (int i = 0; i < 2; i++)
#pragma unroll
                for (int j = 0; j < 4; j++)
                    wmma::mma_sync(acc[i][j], a[i], b[j], acc[i][j]);
        }
        __syncthreads();
    }
    // epilogue
#pragma unroll
    for (int i = 0; i < 2; i++)
#pragma unroll
        for (int j = 0; j < 4; j++) {
            wmma::store_matrix_sync(&stage[w][0][0], acc[i][j], 16, wmma::mem_row_major);
            __syncwarp();
            for (int e = lane; e < 256; e += 32) {
                int r = e >> 4, c = e & 15;
                int gm = m0 + wm * 32 + i * 16 + r;
                int gn = n0 + wn * 64 + j * 16 + c;
                float val = stage[w][r][c] + bias[gn];
                if (gate) val = resid[(size_t)gm * ldc + gn] + gate[gn] * val;
                C[(size_t)gm * ldc + gn] = val;
            }
            __syncwarp();
        }
}

// ---------------- 3) q/k rmsnorm + rope, v copy; [H][L][D] half --------------
__global__ void k_qkv(const float* __restrict__ pe,
                      const float* __restrict__ qs,
                      const float* __restrict__ ks) {
    int l = blockIdx.x, hh = blockIdx.y, d = threadIdx.x;
    const float* hrow = g_h + (size_t)l * W1N;
    float qv = hrow[hh * HD + d];
    float kv = hrow[HID + hh * HD + d];
    float vv = hrow[2 * HID + hh * HD + d];
    float sq = qv * qv, sk = kv * kv;
    for (int o = 16; o > 0; o >>= 1) {
        sq += __shfl_xor_sync(~0u, sq, o);
        sk += __shfl_xor_sync(~0u, sk, o);
    }
    __shared__ float wsq[4], wsk[4];
    int w = d >> 5;
    if ((d & 31) == 0) { wsq[w] = sq; wsk[w] = sk; }
    __syncthreads();
    float msq = (wsq[0] + wsq[1] + wsq[2] + wsq[3]) * (1.f / HD);
    float msk = (wsk[0] + wsk[1] + wsk[2] + wsk[3]) * (1.f / HD);
    __shared__ float nq[HD], nk[HD];
    nq[d] = qv * rsqrtf(msq + 1e-6f) * qs[d];
    nk[d] = kv * rsqrtf(msk + 1e-6f) * ks[d];
    __syncthreads();
    int c = d >> 1, r = d & 1;
    const float* pp = pe + ((size_t)l * 64 + c) * 4 + r * 2;
    float qr = pp[0] * nq[2 * c] + pp[1] * nq[2 * c + 1];
    float kr = pp[0] * nk[2 * c] + pp[1] * nk[2 * c + 1];
    size_t base = ((size_t)hh * LSEQ + l) * HD + d;
    g_q[base] = __float2half_rn(qr * 0.08838834764831845f);  // * D^-0.5
    g_k[base] = __float2half_rn(kr);
    g_v[base] = __float2half_rn(vv);
}

// ---------------- 4) attention: block = (16 q rows, 1 head), exact softmax ---
// dyn smem: S[16][SLD] fp32 | Qs[16][136] half | KVs[128][136] half
#define QS_H 136
#define KV_H 136
#define ATTN_DSMEM (16 * SLD * 4 + (16 * QS_H + 128 * KV_H) * 2)

__global__ void __launch_bounds__(256) k_attn() {
    extern __shared__ float dsm[];
    float*  S   = dsm;                                    // 16 x SLD fp32
    __half* Qs  = reinterpret_cast<__half*>(S + 16 * SLD);
    __half* KVs = Qs + 16 * QS_H;
    __shared__ float Os[8][16][16];
    __shared__ float inv_l[16];

    int tid = threadIdx.x, w = tid >> 5, lane = tid & 31;
    int hh = blockIdx.y;
    int q0 = blockIdx.x * 16;
    const __half* Qg = g_q + ((size_t)hh * LSEQ + q0) * HD;
    const __half* Kg = g_k + (size_t)hh * LSEQ * HD;
    const __half* Vg = g_v + (size_t)hh * LSEQ * HD;

    // load Q tile (16x128 halves = 256 16B chunks)
    {
        int r = tid >> 4, c8 = (tid & 15) * 8;
        cp16(saddr(Qs + r * QS_H + c8), Qg + r * HD + c8);
    }
    cp_commit();
    cp_wait0();
    __syncthreads();

    // copy slot: 2 threads per row, each covers 64 halves (8 x 16B)
    int cr = tid >> 1, cc = (tid & 1) * 64;

    // phase 1: scores S[16][2048] = Q @ K^T, staging K 128 rows at a time
    for (int t = 0; t < 16; ++t) {
        {
            const __half* src = Kg + (size_t)(t * 128 + cr) * HD + cc;
            unsigned dst = saddr(KVs + cr * KV_H + cc);
#pragma unroll
            for (int p = 0; p < 8; ++p) cp16(dst + p * 16, src + p * 8);
        }
        cp_commit();
        cp_wait0();
        __syncthreads();
        wmma::fragment<wmma::accumulator, 16, 16, 16, float> sacc;
        wmma::fill_fragment(sacc, 0.f);
#pragma unroll
        for (int kk = 0; kk < HD; kk += 16) {
            wmma::fragment<wmma::matrix_a, 16, 16, 16, __half, wmma::row_major> a;
            wmma::fragment<wmma::matrix_b, 16, 16, 16, __half, wmma::col_major> b;
            wmma::load_matrix_sync(a, Qs + kk, QS_H);
            wmma::load_matrix_sync(b, KVs + (w * 16) * KV_H + kk, KV_H);
            wmma::mma_sync(sacc, a, b, sacc);
        }
        wmma::store_matrix_sync(S + t * 128 + w * 16, sacc, SLD, wmma::mem_row_major);
        __syncthreads();
    }

    // phase 2: exact softmax; warp w owns rows 2w, 2w+1.
    // Pass 1: max. Pass 2: e=exp, sum, store e (fp32, in place).
    // Pass 3: convert fp32 e -> fp16 in place (aliased low half of each row;
    //         per-iteration loads precede stores, rows are warp-private -> safe).
#pragma unroll
    for (int rr = 0; rr < 2; ++rr) {
        int row = w * 2 + rr;
        float* Sr = S + (size_t)row * SLD;
        __half* Pr = reinterpret_cast<__half*>(Sr);
        float m = -1e30f;
        for (int i = lane; i < LSEQ; i += 32) m = fmaxf(m, Sr[i]);
        for (int o = 16; o > 0; o >>= 1) m = fmaxf(m, __shfl_xor_sync(~0u, m, o));
        float sum = 0.f;
        for (int i = lane; i < LSEQ; i += 32) {
            float e = __expf(Sr[i] - m);
            sum += e;
            Sr[i] = e;
        }
        for (int o = 16; o > 0; o >>= 1) sum += __shfl_xor_sync(~0u, sum, o);
        if (lane == 0) inv_l[row] = 1.f / sum;
        for (int i = lane; i < LSEQ; i += 32) {
            float e = Sr[i];
            Pr[i] = __float2half_rn(e);
        }
    }
    __syncthreads();

    // phase 3: O = P @ V, staging V 128 rows at a time; warp w owns cols w*16..+16
    __half* Ph = reinterpret_cast<__half*>(S);   // row stride SLD*2 halves
    wmma::fragment<wmma::accumulator, 16, 16, 16, float> oacc;
    wmma::fill_fragment(oacc, 0.f);
    for (int t = 0; t < 16; ++t) {
        {
            const __half* src = Vg + (size_t)(t * 128 + cr) * HD + cc;
            unsigned dst = saddr(KVs + cr * KV_H + cc);
#pragma unroll
            for (int p = 0; p < 8; ++p) cp16(dst + p * 16, src + p * 8);
        }
        cp_commit();
        cp_wait0();
        __syncthreads();
#pragma unroll
        for (int kk = 0; kk < 128; kk += 16) {
            wmma::fragment<wmma::matrix_a, 16, 16, 16, __half, wmma::row_major> a;
            wmma::fragment<wmma::matrix_b, 16, 16, 16, __half, wmma::row_major> b;
            wmma::load_matrix_sync(a, Ph + t * 128 + kk, SLD * 2);
            wmma::load_matrix_sync(b, KVs + kk * KV_H + w * 16, KV_H);
            wmma::mma_sync(oacc, a, b, oacc);
        }
        __syncthreads();
    }
    wmma::store_matrix_sync(&Os[w][0][0], oacc, 16, wmma::mem_row_major);
    __syncwarp();
    for (int e = lane; e < 256; e += 32) {
        int r = e >> 4, c = e & 15;
        float val = Os[w][r][c] * inv_l[r];
        g_cat[(size_t)(q0 + r) * CATN + hh * HD + w * 16 + c] = __float2half_rn(val);
    }
}

// ---------------- 5) gelu(mlp) into concat buffer (fp16) ---------------------
__global__ void k_gelu() {
    size_t total = (size_t)LSEQ * MLPD;
    for (size_t idx = (size_t)blockIdx.x * 256 + threadIdx.x; idx < total;
         idx += (size_t)gridDim.x * 256) {
        size_t l = idx / MLPD, j = idx % MLPD;
        float v = g_h[l * W1N + 3 * HID + j];
        float t = 0.7978845608028654f * (v + 0.044715f * v * v * v);
        float g = 0.5f * v * (1.f + tanhf(t));
        g_cat[l * CATN + HID + j] = __float2half_rn(g);
    }
}

// ---------------- launch -----------------------------------------------------
extern "C" void kernel_launch(void* const* d_in, const int* in_sizes, int n_in,
                              void* d_out, int out_size) {
    const float* x     = (const float*)d_in[0];
    const float* vec   = (const float*)d_in[1];
    const float* pe    = (const float*)d_in[2];
    const float* mod_w = (const float*)d_in[3];
    const float* mod_b = (const float*)d_in[4];
    const float* ln_g  = (const float*)d_in[5];
    const float* ln_b  = (const float*)d_in[6];
    const float* w1    = (const float*)d_in[7];
    const float* b1    = (const float*)d_in[8];
    const float* q_s   = (const float*)d_in[9];
    const float* k_s   = (const float*)d_in[10];
    const float* w2    = (const float*)d_in[11];
    const float* b2    = (const float*)d_in[12];
    float* out = (float*)d_out;

    __half *p_xmod, *p_cat, *p_w1h, *p_w2h;
    float *p_h, *p_mod;
    cudaGetSymbolAddress((void**)&p_xmod, g_xmod);
    cudaGetSymbolAddress((void**)&p_h,    g_h);
    cudaGetSymbolAddress((void**)&p_cat,  g_cat);
    cudaGetSymbolAddress((void**)&p_mod,  g_mod);
    cudaGetSymbolAddress((void**)&p_w1h,  g_w1h);
    cudaGetSymbolAddress((void**)&p_w2h,  g_w2h);

    cudaFuncSetAttribute(k_attn, cudaFuncAttributeMaxDynamicSharedMemorySize,
                         ATTN_DSMEM);
    cudaFuncSetAttribute(k_gemm, cudaFuncAttributeMaxDynamicSharedMemorySize,
                         GEMM_DSMEM);

    k_convert_h<<<4096, 256>>>(w1, p_w1h, (size_t)HID * W1N / 8);
    k_convert_h<<<4096, 256>>>(w2, p_w2h, (size_t)CATN * HID / 8);
    k_mod_gemv<<<144, 256>>>(vec, mod_w, mod_b);
    k_ln_mod<<<LSEQ, 256>>>(x, ln_g, ln_b);
    k_nop<<<1, 1>>>();   // keeps ncu -s 5 -c 1 on GEMM1
    // h = x_mod @ w1 + b1
    k_gemm<<<dim3(16, 168), 256, GEMM_DSMEM>>>(p_xmod, HID, p_w1h, W1N, p_h,
                                               W1N, HID, b1, nullptr, nullptr);
    k_qkv<<<dim3(LSEQ, NH), 128>>>(pe, q_s, k_s);
    k_attn<<<dim3(128, NH), 256, ATTN_DSMEM>>>();
    k_gelu<<<12288, 256>>>();
    // out = x + gate * (cat @ w2 + b2)
    k_gemm<<<dim3(16, 24), 256, GEMM_DSMEM>>>(p_cat, CATN, p_w2h, HID, out,
                                              HID, CATN, b2, p_mod + 2 * HID, x);
    (void)in_sizes; (void)n_in; (void)out_size;
}

// round 7
// speedup vs baseline: 2.9060x; 1.0639x over previous
#include <cuda_runtime.h>
#include <cstdint>
#include <stdint.h>
#include <cuda_fp16.h>
#include <mma.h>
#include <math.h>

using namespace nvcuda;

#define LSEQ 2048
#define HID  3072
#define NH   24
#define HD   128
#define MLPD 12288
#define W1N  21504   // 3*HID + MLP
#define QKVN 9216    // 3*HID
#define CATN 15360   // HID + MLP
#define SLD  2056    // padded score-row stride (floats)

// ---------------- scratch (device globals; no allocations allowed) ----------
__device__ float  g_mod[3 * HID];
__device__ __half g_xmod[(size_t)LSEQ * HID];
__device__ __half g_h[(size_t)LSEQ * QKVN];          // qkv part only, fp16
__device__ __half g_q[(size_t)NH * LSEQ * HD];
__device__ __half g_k[(size_t)NH * LSEQ * HD];
__device__ __half g_v[(size_t)NH * LSEQ * HD];
__device__ __half g_cat[(size_t)LSEQ * CATN];
__device__ __half g_w1h[(size_t)HID * W1N];
__device__ __half g_w2h[(size_t)CATN * HID];

// ---------------- cp.async helpers ------------------------------------------
__device__ __forceinline__ void cp16(unsigned dst, const void* src) {
    asm volatile("cp.async.cg.shared.global [%0], [%1], 16;\n" :: "r"(dst), "l"(src));
}
__device__ __forceinline__ void cp_commit() {
    asm volatile("cp.async.commit_group;\n");
}
__device__ __forceinline__ void cp_wait0() {
    asm volatile("cp.async.wait_group 0;\n");
}
__device__ __forceinline__ void cp_wait1() {
    asm volatile("cp.async.wait_group 1;\n");
}
__device__ __forceinline__ unsigned saddr(const void* p) {
    return (unsigned)__cvta_generic_to_shared(p);
}

// ---------------- 0) fp32 -> fp16 weight conversion --------------------------
__global__ void k_convert_h(const float* __restrict__ in, __half* __restrict__ out,
                            size_t n8) {
    const float4* in4 = reinterpret_cast<const float4*>(in);
    uint4* out4 = reinterpret_cast<uint4*>(out);
    for (size_t i = (size_t)blockIdx.x * 256 + threadIdx.x; i < n8;
         i += (size_t)gridDim.x * 256) {
        float4 a = in4[2 * i], b = in4[2 * i + 1];
        __half2 h0 = __floats2half2_rn(a.x, a.y);
        __half2 h1 = __floats2half2_rn(a.z, a.w);
        __half2 h2 = __floats2half2_rn(b.x, b.y);
        __half2 h3 = __floats2half2_rn(b.z, b.w);
        uint4 o;
        o.x = *reinterpret_cast<unsigned*>(&h0);
        o.y = *reinterpret_cast<unsigned*>(&h1);
        o.z = *reinterpret_cast<unsigned*>(&h2);
        o.w = *reinterpret_cast<unsigned*>(&h3);
        out4[i] = o;
    }
}

// ---------------- 1) mod = silu(vec) @ mod_w + mod_b ------------------------
__global__ void k_mod_gemv(const float* __restrict__ vec,
                           const float* __restrict__ mw,
                           const float* __restrict__ mb) {
    __shared__ float sv[HID];
    int tid = threadIdx.x;
    for (int i = tid; i < HID; i += 256) {
        float v = vec[i];
        sv[i] = v / (1.f + expf(-v));
    }
    __syncthreads();
    int j = tid & 63, ky = tid >> 6;
    int col = blockIdx.x * 64 + j;
    const float* wp = mw + col;
    float acc = 0.f;
    int i0 = ky * 768;
#pragma unroll 4
    for (int i = i0; i < i0 + 768; ++i)
        acc += sv[i] * wp[(size_t)i * (3 * HID)];
    __shared__ float red[4][64];
    red[ky][j] = acc;
    __syncthreads();
    if (ky == 0)
        g_mod[col] = red[0][j] + red[1][j] + red[2][j] + red[3][j] + mb[col];
}

// ---------------- 2) LayerNorm + modulate (writes fp16) ----------------------
__global__ void k_ln_mod(const float* __restrict__ x,
                         const float* __restrict__ gamma,
                         const float* __restrict__ beta) {
    int l = blockIdx.x;
    const float* xr = x + (size_t)l * HID;
    float s = 0.f, ss = 0.f;
    for (int c = threadIdx.x; c < HID; c += 256) {
        float v = xr[c];
        s += v; ss += v * v;
    }
    __shared__ float rs[8], rss[8];
    for (int o = 16; o > 0; o >>= 1) {
        s  += __shfl_xor_sync(~0u, s, o);
        ss += __shfl_xor_sync(~0u, ss, o);
    }
    int w = threadIdx.x >> 5;
    if ((threadIdx.x & 31) == 0) { rs[w] = s; rss[w] = ss; }
    __syncthreads();
    float S = 0.f, SS = 0.f;
#pragma unroll
    for (int i = 0; i < 8; ++i) { S += rs[i]; SS += rss[i]; }
    float mu   = S * (1.f / HID);
    float var  = SS * (1.f / HID) - mu * mu;
    float rstd = rsqrtf(var + 1e-6f);
    __half* o = g_xmod + (size_t)l * HID;
    for (int c = threadIdx.x; c < HID; c += 256) {
        float ln = (xr[c] - mu) * rstd * gamma[c] + beta[c];
        o[c] = __float2half_rn((1.f + g_mod[HID + c]) * ln + g_mod[c]);
    }
}

// ---------------- FP16 GEMM: 128x256 CTA tile, 3-stage, 64x64 warp tiles -----
// mode 0: C = A@B + b1; cols < QKVN -> g_h (fp16); cols >= QKVN -> gelu -> g_cat
// mode 1: C = resid + gate * (A@B + bias)  (fp32 out)
#define BM 128
#define BN 256
#define BK 32
#define NSTG 3
#define AS_H 40
#define BS_H 264
#define STG_A (BM * AS_H)
#define STG_B (BK * BS_H)
#define GEMM_DSMEM (NSTG * (STG_A + STG_B) * 2)

__global__ void __launch_bounds__(256, 1) k_gemm(
    const __half* __restrict__ A, int lda,
    const __half* __restrict__ B, int ldb, int K,
    const float* __restrict__ bias, int mode,
    float* __restrict__ f_out,
    const float* __restrict__ gate,
    const float* __restrict__ resid) {
    extern __shared__ __half hsm[];
    __shared__ float stage[8][16][16];

    int tid = threadIdx.x;
    int m0 = blockIdx.x * BM, n0 = blockIdx.y * BN;
    int w = tid >> 5, lane = tid & 31;
    int wm = w & 1, wn = w >> 1;

    // copy slots
    int ar = tid >> 1, ac = (tid & 1) * 16;   // A: 2 thr/row, 16 halves each
    int br = tid >> 3, bc = (tid & 7) * 32;   // B: 8 thr/row, 32 halves each

    wmma::fragment<wmma::accumulator, 16, 16, 16, float> acc[4][4];
#pragma unroll
    for (int i = 0; i < 4; i++)
#pragma unroll
        for (int j = 0; j < 4; j++) wmma::fill_fragment(acc[i][j], 0.f);

    int nsteps = K / BK;
    auto issue = [&](int s) {
        int k0 = s * BK;
        __half* As = hsm + (s % NSTG) * (STG_A + STG_B);
        __half* Bs = As + STG_A;
        {
            const __half* src = A + (size_t)(m0 + ar) * lda + k0 + ac;
            unsigned dst = saddr(As + ar * AS_H + ac);
            cp16(dst, src);
            cp16(dst + 16, src + 8);
        }
        {
            const __half* src = B + (size_t)(k0 + br) * ldb + n0 + bc;
            unsigned dst = saddr(Bs + br * BS_H + bc);
            cp16(dst, src);
            cp16(dst + 16, src + 8);
            cp16(dst + 32, src + 16);
            cp16(dst + 48, src + 24);
        }
    };

    issue(0); cp_commit();
    issue(1); cp_commit();

    for (int s = 0; s < nsteps; ++s) {
        if (s + 1 < nsteps) cp_wait1(); else cp_wait0();
        __syncthreads();
        if (s + 2 < nsteps) { issue(s + 2); cp_commit(); }
        __half* As = hsm + (s % NSTG) * (STG_A + STG_B);
        __half* Bs = As + STG_A;
#pragma unroll
        for (int kt = 0; kt < 2; ++kt) {
            int kk = kt * 16;
            wmma::fragment<wmma::matrix_a, 16, 16, 16, __half, wmma::row_major> a[4];
            wmma::fragment<wmma::matrix_b, 16, 16, 16, __half, wmma::row_major> b[4];
#pragma unroll
            for (int i = 0; i < 4; i++)
                wmma::load_matrix_sync(a[i], As + (wm * 64 + i * 16) * AS_H + kk, AS_H);
#pragma unroll
            for (int j = 0; j < 4; j++)
                wmma::load_matrix_sync(b[j], Bs + kk * BS_H + wn * 64 + j * 16, BS_H);
#pragma unroll
            for (int i = 0; i < 4; i++)
#pragma unroll
                for (int j = 0; j < 4; j++)
                    wmma::mma_sync(acc[i][j], a[i], b[j], acc[i][j]);
        }
    }
    __syncthreads();

    // epilogue
    bool isgelu = (mode == 0) && (n0 >= QKVN);
#pragma unroll
    for (int i = 0; i < 4; i++)
#pragma unroll
        for (int j = 0; j < 4; j++) {
            wmma::store_matrix_sync(&stage[w][0][0], acc[i][j], 16, wmma::mem_row_major);
            __syncwarp();
            for (int e = lane; e < 256; e += 32) {
                int r = e >> 4, c = e & 15;
                int gm = m0 + wm * 64 + i * 16 + r;
                int gn = n0 + wn * 64 + j * 16 + c;
                float val = stage[w][r][c] + bias[gn];
                if (mode == 0) {
                    if (!isgelu) {
                        g_h[(size_t)gm * QKVN + gn] = __float2half_rn(val);
                    } else {
                        float t = 0.7978845608028654f * (val + 0.044715f * val * val * val);
                        float g = 0.5f * val * (1.f + tanhf(t));
                        g_cat[(size_t)gm * CATN + HID + (gn - QKVN)] = __float2half_rn(g);
                    }
                } else {
                    f_out[(size_t)gm * HID + gn] =
                        resid[(size_t)gm * HID + gn] + gate[gn] * val;
                }
            }
            __syncwarp();
        }
}

// ---------------- 3) q/k rmsnorm + rope, v copy; [H][L][D] half --------------
__global__ void k_qkv(const float* __restrict__ pe,
                      const float* __restrict__ qs,
                      const float* __restrict__ ks) {
    int l = blockIdx.x, hh = blockIdx.y, d = threadIdx.x;
    const __half* hrow = g_h + (size_t)l * QKVN;
    float qv = __half2float(hrow[hh * HD + d]);
    float kv = __half2float(hrow[HID + hh * HD + d]);
    float vv = __half2float(hrow[2 * HID + hh * HD + d]);
    float sq = qv * qv, sk = kv * kv;
    for (int o = 16; o > 0; o >>= 1) {
        sq += __shfl_xor_sync(~0u, sq, o);
        sk += __shfl_xor_sync(~0u, sk, o);
    }
    __shared__ float wsq[4], wsk[4];
    int w = d >> 5;
    if ((d & 31) == 0) { wsq[w] = sq; wsk[w] = sk; }
    __syncthreads();
    float msq = (wsq[0] + wsq[1] + wsq[2] + wsq[3]) * (1.f / HD);
    float msk = (wsk[0] + wsk[1] + wsk[2] + wsk[3]) * (1.f / HD);
    __shared__ float nq[HD], nk[HD];
    nq[d] = qv * rsqrtf(msq + 1e-6f) * qs[d];
    nk[d] = kv * rsqrtf(msk + 1e-6f) * ks[d];
    __syncthreads();
    int c = d >> 1, r = d & 1;
    const float* pp = pe + ((size_t)l * 64 + c) * 4 + r * 2;
    float qr = pp[0] * nq[2 * c] + pp[1] * nq[2 * c + 1];
    float kr = pp[0] * nk[2 * c] + pp[1] * nk[2 * c + 1];
    size_t base = ((size_t)hh * LSEQ + l) * HD + d;
    g_q[base] = __float2half_rn(qr * 0.08838834764831845f);  // * D^-0.5
    g_k[base] = __float2half_rn(kr);
    g_v[base] = __float2half_rn(vv);
}

// ---------------- 4) attention: block = (16 q rows, 1 head), exact softmax ---
#define QS_H 136
#define KV_H 136
#define ATTN_DSMEM (16 * SLD * 4 + (16 * QS_H + 128 * KV_H) * 2)

__global__ void __launch_bounds__(256) k_attn() {
    extern __shared__ float dsm[];
    float*  S   = dsm;                                    // 16 x SLD fp32
    __half* Qs  = reinterpret_cast<__half*>(S + 16 * SLD);
    __half* KVs = Qs + 16 * QS_H;
    __shared__ float Os[8][16][16];
    __shared__ float inv_l[16];

    int tid = threadIdx.x, w = tid >> 5, lane = tid & 31;
    int hh = blockIdx.y;
    int q0 = blockIdx.x * 16;
    const __half* Qg = g_q + ((size_t)hh * LSEQ + q0) * HD;
    const __half* Kg = g_k + (size_t)hh * LSEQ * HD;
    const __half* Vg = g_v + (size_t)hh * LSEQ * HD;

    {
        int r = tid >> 4, c8 = (tid & 15) * 8;
        cp16(saddr(Qs + r * QS_H + c8), Qg + r * HD + c8);
    }
    cp_commit();
    cp_wait0();
    __syncthreads();

    int cr = tid >> 1, cc = (tid & 1) * 64;

    // phase 1: scores S[16][2048] = Q @ K^T
    for (int t = 0; t < 16; ++t) {
        {
            const __half* src = Kg + (size_t)(t * 128 + cr) * HD + cc;
            unsigned dst = saddr(KVs + cr * KV_H + cc);
#pragma unroll
            for (int p = 0; p < 8; ++p) cp16(dst + p * 16, src + p * 8);
        }
        cp_commit();
        cp_wait0();
        __syncthreads();
        wmma::fragment<wmma::accumulator, 16, 16, 16, float> sacc;
        wmma::fill_fragment(sacc, 0.f);
#pragma unroll
        for (int kk = 0; kk < HD; kk += 16) {
            wmma::fragment<wmma::matrix_a, 16, 16, 16, __half, wmma::row_major> a;
            wmma::fragment<wmma::matrix_b, 16, 16, 16, __half, wmma::col_major> b;
            wmma::load_matrix_sync(a, Qs + kk, QS_H);
            wmma::load_matrix_sync(b, KVs + (w * 16) * KV_H + kk, KV_H);
            wmma::mma_sync(sacc, a, b, sacc);
        }
        wmma::store_matrix_sync(S + t * 128 + w * 16, sacc, SLD, wmma::mem_row_major);
        __syncthreads();
    }

    // phase 2: exact softmax; fp32 -> fp16 in place
#pragma unroll
    for (int rr = 0; rr < 2; ++rr) {
        int row = w * 2 + rr;
        float* Sr = S + (size_t)row * SLD;
        __half* Pr = reinterpret_cast<__half*>(Sr);
        float m = -1e30f;
        for (int i = lane; i < LSEQ; i += 32) m = fmaxf(m, Sr[i]);
        for (int o = 16; o > 0; o >>= 1) m = fmaxf(m, __shfl_xor_sync(~0u, m, o));
        float sum = 0.f;
        for (int i = lane; i < LSEQ; i += 32) {
            float e = __expf(Sr[i] - m);
            sum += e;
            Sr[i] = e;
        }
        for (int o = 16; o > 0; o >>= 1) sum += __shfl_xor_sync(~0u, sum, o);
        if (lane == 0) inv_l[row] = 1.f / sum;
        for (int i = lane; i < LSEQ; i += 32) {
            float e = Sr[i];
            Pr[i] = __float2half_rn(e);
        }
    }
    __syncthreads();

    // phase 3: O = P @ V
    __half* Ph = reinterpret_cast<__half*>(S);   // row stride SLD*2 halves
    wmma::fragment<wmma::accumulator, 16, 16, 16, float> oacc;
    wmma::fill_fragment(oacc, 0.f);
    for (int t = 0; t < 16; ++t) {
        {
            const __half* src = Vg + (size_t)(t * 128 + cr) * HD + cc;
            unsigned dst = saddr(KVs + cr * KV_H + cc);
#pragma unroll
            for (int p = 0; p < 8; ++p) cp16(dst + p * 16, src + p * 8);
        }
        cp_commit();
        cp_wait0();
        __syncthreads();
#pragma unroll
        for (int kk = 0; kk < 128; kk += 16) {
            wmma::fragment<wmma::matrix_a, 16, 16, 16, __half, wmma::row_major> a;
            wmma::fragment<wmma::matrix_b, 16, 16, 16, __half, wmma::row_major> b;
            wmma::load_matrix_sync(a, Ph + t * 128 + kk, SLD * 2);
            wmma::load_matrix_sync(b, KVs + kk * KV_H + w * 16, KV_H);
            wmma::mma_sync(oacc, a, b, oacc);
        }
        __syncthreads();
    }
    wmma::store_matrix_sync(&Os[w][0][0], oacc, 16, wmma::mem_row_major);
    __syncwarp();
    for (int e = lane; e < 256; e += 32) {
        int r = e >> 4, c = e & 15;
        float val = Os[w][r][c] * inv_l[r];
        g_cat[(size_t)(q0 + r) * CATN + hh * HD + w * 16 + c] = __float2half_rn(val);
    }
}

// ---------------- launch -----------------------------------------------------
extern "C" void kernel_launch(void* const* d_in, const int* in_sizes, int n_in,
                              void* d_out, int out_size) {
    const float* x     = (const float*)d_in[0];
    const float* vec   = (const float*)d_in[1];
    const float* pe    = (const float*)d_in[2];
    const float* mod_w = (const float*)d_in[3];
    const float* mod_b = (const float*)d_in[4];
    const float* ln_g  = (const float*)d_in[5];
    const float* ln_b  = (const float*)d_in[6];
    const float* w1    = (const float*)d_in[7];
    const float* b1    = (const float*)d_in[8];
    const float* q_s   = (const float*)d_in[9];
    const float* k_s   = (const float*)d_in[10];
    const float* w2    = (const float*)d_in[11];
    const float* b2    = (const float*)d_in[12];
    float* out = (float*)d_out;

    __half *p_xmod, *p_cat, *p_w1h, *p_w2h;
    float *p_mod;
    cudaGetSymbolAddress((void**)&p_xmod, g_xmod);
    cudaGetSymbolAddress((void**)&p_cat,  g_cat);
    cudaGetSymbolAddress((void**)&p_mod,  g_mod);
    cudaGetSymbolAddress((void**)&p_w1h,  g_w1h);
    cudaGetSymbolAddress((void**)&p_w2h,  g_w2h);

    cudaFuncSetAttribute(k_attn, cudaFuncAttributeMaxDynamicSharedMemorySize,
                         ATTN_DSMEM);
    cudaFuncSetAttribute(k_gemm, cudaFuncAttributeMaxDynamicSharedMemorySize,
                         GEMM_DSMEM);

    k_mod_gemv<<<144, 256>>>(vec, mod_w, mod_b);                       // 1
    k_convert_h<<<4096, 256>>>(w1, p_w1h, (size_t)HID * W1N / 8);      // 2
    k_ln_mod<<<LSEQ, 256>>>(x, ln_g, ln_b);                            // 3
    // h|gelu(mlp) = x_mod @ w1 + b1       (launch #4 -> profiled)
    k_gemm<<<dim3(16, 84), 256, GEMM_DSMEM>>>(p_xmod, HID, p_w1h, W1N,
                                              HID, b1, 0,
                                              nullptr, nullptr, nullptr);
    k_qkv<<<dim3(LSEQ, NH), 128>>>(pe, q_s, k_s);                      // 5
    k_attn<<<dim3(128, NH), 256, ATTN_DSMEM>>>();                      // 6
    k_convert_h<<<4096, 256>>>(w2, p_w2h, (size_t)CATN * HID / 8);     // 7
    // out = x + gate * (cat @ w2 + b2)
    k_gemm<<<dim3(16, 12), 256, GEMM_DSMEM>>>(p_cat, CATN, p_w2h, HID,
                                              CATN, b2, 1,
                                              out, p_mod + 2 * HID, x);
    (void)in_sizes; (void)n_in; (void)out_size;
}

// round 8
// speedup vs baseline: 3.6269x; 1.2481x over previous
#include <cuda_runtime.h>
#include <cstdint>
#include <stdint.h>
#include <cuda_fp16.h>
#include <mma.h>
#include <math.h>

using namespace nvcuda;

#define LSEQ 2048
#define HID  3072
#define NH   24
#define HD   128
#define MLPD 12288
#define W1N  21504   // 3*HID + MLP
#define QKVN 9216    // 3*HID
#define CATN 15360   // HID + MLP
#define SLD  2056    // padded score-row stride (floats)

// ---------------- scratch (device globals; no allocations allowed) ----------
__device__ float  g_mod[3 * HID];
__device__ __half g_xmod[(size_t)LSEQ * HID];
__device__ __half g_h[(size_t)LSEQ * QKVN];          // qkv part only, fp16
__device__ __half g_q[(size_t)NH * LSEQ * HD];
__device__ __half g_k[(size_t)NH * LSEQ * HD];
__device__ __half g_v[(size_t)NH * LSEQ * HD];
__device__ __half g_cat[(size_t)LSEQ * CATN];
__device__ __half g_w1h[(size_t)HID * W1N];
__device__ __half g_w2h[(size_t)CATN * HID];

// ---------------- cp.async helpers ------------------------------------------
__device__ __forceinline__ void cp16(unsigned dst, const void* src) {
    asm volatile("cp.async.cg.shared.global [%0], [%1], 16;\n" :: "r"(dst), "l"(src));
}
__device__ __forceinline__ void cp_commit() {
    asm volatile("cp.async.commit_group;\n");
}
__device__ __forceinline__ void cp_wait0() {
    asm volatile("cp.async.wait_group 0;\n");
}
__device__ __forceinline__ void cp_wait1() {
    asm volatile("cp.async.wait_group 1;\n");
}
__device__ __forceinline__ unsigned saddr(const void* p) {
    return (unsigned)__cvta_generic_to_shared(p);
}

// ---------------- 0) fp32 -> fp16 weight conversion --------------------------
__global__ void k_convert_h(const float* __restrict__ in, __half* __restrict__ out,
                            size_t n8) {
    const float4* in4 = reinterpret_cast<const float4*>(in);
    uint4* out4 = reinterpret_cast<uint4*>(out);
    for (size_t i = (size_t)blockIdx.x * 256 + threadIdx.x; i < n8;
         i += (size_t)gridDim.x * 256) {
        float4 a = in4[2 * i], b = in4[2 * i + 1];
        __half2 h0 = __floats2half2_rn(a.x, a.y);
        __half2 h1 = __floats2half2_rn(a.z, a.w);
        __half2 h2 = __floats2half2_rn(b.x, b.y);
        __half2 h3 = __floats2half2_rn(b.z, b.w);
        uint4 o;
        o.x = *reinterpret_cast<unsigned*>(&h0);
        o.y = *reinterpret_cast<unsigned*>(&h1);
        o.z = *reinterpret_cast<unsigned*>(&h2);
        o.w = *reinterpret_cast<unsigned*>(&h3);
        out4[i] = o;
    }
}

// ---------------- 1) mod = silu(vec) @ mod_w + mod_b ------------------------
__global__ void k_mod_gemv(const float* __restrict__ vec,
                           const float* __restrict__ mw,
                           const float* __restrict__ mb) {
    __shared__ float sv[HID];
    int tid = threadIdx.x;
    for (int i = tid; i < HID; i += 256) {
        float v = vec[i];
        sv[i] = v / (1.f + expf(-v));
    }
    __syncthreads();
    int j = tid & 63, ky = tid >> 6;
    int col = blockIdx.x * 64 + j;
    const float* wp = mw + col;
    float acc = 0.f;
    int i0 = ky * 768;
#pragma unroll 4
    for (int i = i0; i < i0 + 768; ++i)
        acc += sv[i] * wp[(size_t)i * (3 * HID)];
    __shared__ float red[4][64];
    red[ky][j] = acc;
    __syncthreads();
    if (ky == 0)
        g_mod[col] = red[0][j] + red[1][j] + red[2][j] + red[3][j] + mb[col];
}

// ---------------- 2) LayerNorm + modulate (writes fp16) ----------------------
__global__ void k_ln_mod(const float* __restrict__ x,
                         const float* __restrict__ gamma,
                         const float* __restrict__ beta) {
    int l = blockIdx.x;
    const float* xr = x + (size_t)l * HID;
    float s = 0.f, ss = 0.f;
    for (int c = threadIdx.x; c < HID; c += 256) {
        float v = xr[c];
        s += v; ss += v * v;
    }
    __shared__ float rs[8], rss[8];
    for (int o = 16; o > 0; o >>= 1) {
        s  += __shfl_xor_sync(~0u, s, o);
        ss += __shfl_xor_sync(~0u, ss, o);
    }
    int w = threadIdx.x >> 5;
    if ((threadIdx.x & 31) == 0) { rs[w] = s; rss[w] = ss; }
    __syncthreads();
    float S = 0.f, SS = 0.f;
#pragma unroll
    for (int i = 0; i < 8; ++i) { S += rs[i]; SS += rss[i]; }
    float mu   = S * (1.f / HID);
    float var  = SS * (1.f / HID) - mu * mu;
    float rstd = rsqrtf(var + 1e-6f);
    __half* o = g_xmod + (size_t)l * HID;
    for (int c = threadIdx.x; c < HID; c += 256) {
        float ln = (xr[c] - mu) * rstd * gamma[c] + beta[c];
        o[c] = __float2half_rn((1.f + g_mod[HID + c]) * ln + g_mod[c]);
    }
}

// ---------------- FP16 GEMM: 128x128 CTA tile, 3-stage, 32x64 warp tiles -----
// 8 warps (4 along M x 2 along N). 2 CTAs/SM.
// mode 0: C = A@B + b1; cols < QKVN -> g_h (fp16); cols >= QKVN -> gelu -> g_cat
// mode 1: C = resid + gate * (A@B + bias)  (fp32 out)
#define BM 128
#define BN 128
#define BK 32
#define NSTG 3
#define AS_H 40
#define BS_H 136
#define STG_A (BM * AS_H)
#define STG_B (BK * BS_H)
#define GEMM_DSMEM (NSTG * (STG_A + STG_B) * 2)

__global__ void __launch_bounds__(256, 2) k_gemm(
    const __half* __restrict__ A, int lda,
    const __half* __restrict__ B, int ldb, int K,
    const float* __restrict__ bias, int mode,
    float* __restrict__ f_out,
    const float* __restrict__ gate,
    const float* __restrict__ resid) {
    extern __shared__ __half hsm[];
    __shared__ float stage[8][16][16];

    int tid = threadIdx.x;
    int m0 = blockIdx.x * BM, n0 = blockIdx.y * BN;
    int w = tid >> 5, lane = tid & 31;
    int wm = w & 3, wn = w >> 2;   // warp tile: rows [wm*32, +32), cols [wn*64, +64)

    // copy slots
    int ar = tid >> 1, ac = (tid & 1) * 16;   // A: 2 thr/row, 16 halves each
    int br = tid >> 3, bc = (tid & 7) * 16;   // B: 8 thr/row, 16 halves each

    wmma::fragment<wmma::accumulator, 16, 16, 16, float> acc[2][4];
#pragma unroll
    for (int i = 0; i < 2; i++)
#pragma unroll
        for (int j = 0; j < 4; j++) wmma::fill_fragment(acc[i][j], 0.f);

    int nsteps = K / BK;
    auto issue = [&](int s) {
        int k0 = s * BK;
        __half* As = hsm + (s % NSTG) * (STG_A + STG_B);
        __half* Bs = As + STG_A;
        {
            const __half* src = A + (size_t)(m0 + ar) * lda + k0 + ac;
            unsigned dst = saddr(As + ar * AS_H + ac);
            cp16(dst, src);
            cp16(dst + 16, src + 8);
        }
        {
            const __half* src = B + (size_t)(k0 + br) * ldb + n0 + bc;
            unsigned dst = saddr(Bs + br * BS_H + bc);
            cp16(dst, src);
            cp16(dst + 16, src + 8);
        }
    };

    issue(0); cp_commit();
    issue(1); cp_commit();

    for (int s = 0; s < nsteps; ++s) {
        if (s + 1 < nsteps) cp_wait1(); else cp_wait0();
        __syncthreads();
        if (s + 2 < nsteps) { issue(s + 2); cp_commit(); }
        __half* As = hsm + (s % NSTG) * (STG_A + STG_B);
        __half* Bs = As + STG_A;
#pragma unroll
        for (int kt = 0; kt < 2; ++kt) {
            int kk = kt * 16;
            wmma::fragment<wmma::matrix_a, 16, 16, 16, __half, wmma::row_major> a[2];
            wmma::fragment<wmma::matrix_b, 16, 16, 16, __half, wmma::row_major> b[4];
#pragma unroll
            for (int i = 0; i < 2; i++)
                wmma::load_matrix_sync(a[i], As + (wm * 32 + i * 16) * AS_H + kk, AS_H);
#pragma unroll
            for (int j = 0; j < 4; j++)
                wmma::load_matrix_sync(b[j], Bs + kk * BS_H + wn * 64 + j * 16, BS_H);
#pragma unroll
            for (int i = 0; i < 2; i++)
#pragma unroll
                for (int j = 0; j < 4; j++)
                    wmma::mma_sync(acc[i][j], a[i], b[j], acc[i][j]);
        }
    }
    __syncthreads();

    // epilogue
    bool isgelu = (mode == 0) && (n0 >= QKVN);
#pragma unroll
    for (int i = 0; i < 2; i++)
#pragma unroll
        for (int j = 0; j < 4; j++) {
            wmma::store_matrix_sync(&stage[w][0][0], acc[i][j], 16, wmma::mem_row_major);
            __syncwarp();
            for (int e = lane; e < 256; e += 32) {
                int r = e >> 4, c = e & 15;
                int gm = m0 + wm * 32 + i * 16 + r;
                int gn = n0 + wn * 64 + j * 16 + c;
                float val = stage[w][r][c] + bias[gn];
                if (mode == 0) {
                    if (!isgelu) {
                        g_h[(size_t)gm * QKVN + gn] = __float2half_rn(val);
                    } else {
                        float t = 0.7978845608028654f * (val + 0.044715f * val * val * val);
                        float g = 0.5f * val * (1.f + tanhf(t));
                        g_cat[(size_t)gm * CATN + HID + (gn - QKVN)] = __float2half_rn(g);
                    }
                } else {
                    f_out[(size_t)gm * HID + gn] =
                        resid[(size_t)gm * HID + gn] + gate[gn] * val;
                }
            }
            __syncwarp();
        }
}

// ---------------- 3) q/k rmsnorm + rope, v copy; [H][L][D] half --------------
__global__ void k_qkv(const float* __restrict__ pe,
                      const float* __restrict__ qs,
                      const float* __restrict__ ks) {
    int l = blockIdx.x, hh = blockIdx.y, d = threadIdx.x;
    const __half* hrow = g_h + (size_t)l * QKVN;
    float qv = __half2float(hrow[hh * HD + d]);
    float kv = __half2float(hrow[HID + hh * HD + d]);
    float vv = __half2float(hrow[2 * HID + hh * HD + d]);
    float sq = qv * qv, sk = kv * kv;
    for (int o = 16; o > 0; o >>= 1) {
        sq += __shfl_xor_sync(~0u, sq, o);
        sk += __shfl_xor_sync(~0u, sk, o);
    }
    __shared__ float wsq[4], wsk[4];
    int w = d >> 5;
    if ((d & 31) == 0) { wsq[w] = sq; wsk[w] = sk; }
    __syncthreads();
    float msq = (wsq[0] + wsq[1] + wsq[2] + wsq[3]) * (1.f / HD);
    float msk = (wsk[0] + wsk[1] + wsk[2] + wsk[3]) * (1.f / HD);
    __shared__ float nq[HD], nk[HD];
    nq[d] = qv * rsqrtf(msq + 1e-6f) * qs[d];
    nk[d] = kv * rsqrtf(msk + 1e-6f) * ks[d];
    __syncthreads();
    int c = d >> 1, r = d & 1;
    const float* pp = pe + ((size_t)l * 64 + c) * 4 + r * 2;
    float qr = pp[0] * nq[2 * c] + pp[1] * nq[2 * c + 1];
    float kr = pp[0] * nk[2 * c] + pp[1] * nk[2 * c + 1];
    size_t base = ((size_t)hh * LSEQ + l) * HD + d;
    g_q[base] = __float2half_rn(qr * 0.08838834764831845f);  // * D^-0.5
    g_k[base] = __float2half_rn(kr);
    g_v[base] = __float2half_rn(vv);
}

// ---------------- 4) attention: block = (16 q rows, 1 head), exact softmax ---
// dyn smem: S[16][SLD] fp32 | Qs[16][136] half | KVs 2x [128][136] half
#define QS_H 136
#define KV_H 136
#define KV_BUF (128 * KV_H)
#define ATTN_DSMEM (16 * SLD * 4 + (16 * QS_H + 2 * KV_BUF) * 2)

__global__ void __launch_bounds__(256) k_attn() {
    extern __shared__ float dsm[];
    float*  S   = dsm;                                    // 16 x SLD fp32
    __half* Qs  = reinterpret_cast<__half*>(S + 16 * SLD);
    __half* KV0 = Qs + 16 * QS_H;

    __shared__ float Os[8][16][16];
    __shared__ float inv_l[16];

    int tid = threadIdx.x, w = tid >> 5, lane = tid & 31;
    int hh = blockIdx.y;
    int q0 = blockIdx.x * 16;
    const __half* Qg = g_q + ((size_t)hh * LSEQ + q0) * HD;
    const __half* Kg = g_k + (size_t)hh * LSEQ * HD;
    const __half* Vg = g_v + (size_t)hh * LSEQ * HD;

    {
        int r = tid >> 4, c8 = (tid & 15) * 8;
        cp16(saddr(Qs + r * QS_H + c8), Qg + r * HD + c8);
    }
    cp_commit();
    cp_wait0();
    __syncthreads();

    int cr = tid >> 1, cc = (tid & 1) * 64;

    auto stage_kv = [&](const __half* base, int t) {
        const __half* src = base + (size_t)(t * 128 + cr) * HD + cc;
        unsigned dst = saddr(KV0 + (t & 1) * KV_BUF + cr * KV_H + cc);
#pragma unroll
        for (int p = 0; p < 8; ++p) cp16(dst + p * 16, src + p * 8);
    };

    // phase 1: scores S[16][2048] = Q @ K^T, double-buffered K staging
    stage_kv(Kg, 0); cp_commit();
    stage_kv(Kg, 1); cp_commit();
    for (int t = 0; t < 16; ++t) {
        if (t + 1 < 16) cp_wait1(); else cp_wait0();
        __syncthreads();
        __half* KVs = KV0 + (t & 1) * KV_BUF;
        wmma::fragment<wmma::accumulator, 16, 16, 16, float> sacc;
        wmma::fill_fragment(sacc, 0.f);
#pragma unroll
        for (int kk = 0; kk < HD; kk += 16) {
            wmma::fragment<wmma::matrix_a, 16, 16, 16, __half, wmma::row_major> a;
            wmma::fragment<wmma::matrix_b, 16, 16, 16, __half, wmma::col_major> b;
            wmma::load_matrix_sync(a, Qs + kk, QS_H);
            wmma::load_matrix_sync(b, KVs + (w * 16) * KV_H + kk, KV_H);
            wmma::mma_sync(sacc, a, b, sacc);
        }
        wmma::store_matrix_sync(S + t * 128 + w * 16, sacc, SLD, wmma::mem_row_major);
        __syncthreads();
        if (t + 2 < 16) { stage_kv(Kg, t + 2); cp_commit(); }
    }

    // phase 2: exact softmax; fp32 -> fp16 in place
#pragma unroll
    for (int rr = 0; rr < 2; ++rr) {
        int row = w * 2 + rr;
        float* Sr = S + (size_t)row * SLD;
        __half* Pr = reinterpret_cast<__half*>(Sr);
        float m = -1e30f;
        for (int i = lane; i < LSEQ; i += 32) m = fmaxf(m, Sr[i]);
        for (int o = 16; o > 0; o >>= 1) m = fmaxf(m, __shfl_xor_sync(~0u, m, o));
        float sum = 0.f;
        for (int i = lane; i < LSEQ; i += 32) {
            float e = __expf(Sr[i] - m);
            sum += e;
            Sr[i] = e;
        }
        for (int o = 16; o > 0; o >>= 1) sum += __shfl_xor_sync(~0u, sum, o);
        if (lane == 0) inv_l[row] = 1.f / sum;
        for (int i = lane; i < LSEQ; i += 32) {
            float e = Sr[i];
            Pr[i] = __float2half_rn(e);
        }
    }
    __syncthreads();

    // phase 3: O = P @ V, double-buffered V staging
    __half* Ph = reinterpret_cast<__half*>(S);   // row stride SLD*2 halves
    wmma::fragment<wmma::accumulator, 16, 16, 16, float> oacc;
    wmma::fill_fragment(oacc, 0.f);
    stage_kv(Vg, 0); cp_commit();
    stage_kv(Vg, 1); cp_commit();
    for (int t = 0; t < 16; ++t) {
        if (t + 1 < 16) cp_wait1(); else cp_wait0();
        __syncthreads();
        __half* KVs = KV0 + (t & 1) * KV_BUF;
#pragma unroll
        for (int kk = 0; kk < 128; kk += 16) {
            wmma::fragment<wmma::matrix_a, 16, 16, 16, __half, wmma::row_major> a;
            wmma::fragment<wmma::matrix_b, 16, 16, 16, __half, wmma::row_major> b;
            wmma::load_matrix_sync(a, Ph + t * 128 + kk, SLD * 2);
            wmma::load_matrix_sync(b, KVs + kk * KV_H + w * 16, KV_H);
            wmma::mma_sync(oacc, a, b, oacc);
        }
        __syncthreads();
        if (t + 2 < 16) { stage_kv(Vg, t + 2); cp_commit(); }
    }
    wmma::store_matrix_sync(&Os[w][0][0], oacc, 16, wmma::mem_row_major);
    __syncwarp();
    for (int e = lane; e < 256; e += 32) {
        int r = e >> 4, c = e & 15;
        float val = Os[w][r][c] * inv_l[r];
        g_cat[(size_t)(q0 + r) * CATN + hh * HD + w * 16 + c] = __float2half_rn(val);
    }
}

// ---------------- launch -----------------------------------------------------
extern "C" void kernel_launch(void* const* d_in, const int* in_sizes, int n_in,
                              void* d_out, int out_size) {
    const float* x     = (const float*)d_in[0];
    const float* vec   = (const float*)d_in[1];
    const float* pe    = (const float*)d_in[2];
    const float* mod_w = (const float*)d_in[3];
    const float* mod_b = (const float*)d_in[4];
    const float* ln_g  = (const float*)d_in[5];
    const float* ln_b  = (const float*)d_in[6];
    const float* w1    = (const float*)d_in[7];
    const float* b1    = (const float*)d_in[8];
    const float* q_s   = (const float*)d_in[9];
    const float* k_s   = (const float*)d_in[10];
    const float* w2    = (const float*)d_in[11];
    const float* b2    = (const float*)d_in[12];
    float* out = (float*)d_out;

    __half *p_xmod, *p_cat, *p_w1h, *p_w2h;
    float *p_mod;
    cudaGetSymbolAddress((void**)&p_xmod, g_xmod);
    cudaGetSymbolAddress((void**)&p_cat,  g_cat);
    cudaGetSymbolAddress((void**)&p_mod,  g_mod);
    cudaGetSymbolAddress((void**)&p_w1h,  g_w1h);
    cudaGetSymbolAddress((void**)&p_w2h,  g_w2h);

    cudaFuncSetAttribute(k_attn, cudaFuncAttributeMaxDynamicSharedMemorySize,
                         ATTN_DSMEM);
    cudaFuncSetAttribute(k_gemm, cudaFuncAttributeMaxDynamicSharedMemorySize,
                         GEMM_DSMEM);

    k_mod_gemv<<<144, 256>>>(vec, mod_w, mod_b);                       // 1
    k_convert_h<<<4096, 256>>>(w1, p_w1h, (size_t)HID * W1N / 8);      // 2
    k_ln_mod<<<LSEQ, 256>>>(x, ln_g, ln_b);                            // 3
    // h|gelu(mlp) = x_mod @ w1 + b1       (launch #4 -> profiled)
    k_gemm<<<dim3(16, 168), 256, GEMM_DSMEM>>>(p_xmod, HID, p_w1h, W1N,
                                               HID, b1, 0,
                                               nullptr, nullptr, nullptr);
    k_qkv<<<dim3(LSEQ, NH), 128>>>(pe, q_s, k_s);                      // 5
    k_attn<<<dim3(128, NH), 256, ATTN_DSMEM>>>();                      // 6
    k_convert_h<<<4096, 256>>>(w2, p_w2h, (size_t)CATN * HID / 8);     // 7
    // out = x + gate * (cat @ w2 + b2)
    k_gemm<<<dim3(16, 24), 256, GEMM_DSMEM>>>(p_cat, CATN, p_w2h, HID,
                                              CATN, b2, 1,
                                              out, p_mod + 2 * HID, x);
    (void)in_sizes; (void)n_in; (void)out_size;
}

// round 9
// speedup vs baseline: 4.1991x; 1.1578x over previous
#include <cuda_runtime.h>
#include <cstdint>
#include <stdint.h>
#include <cuda_fp16.h>
#include <mma.h>
#include <math.h>

using namespace nvcuda;

#define LSEQ 2048
#define HID  3072
#define NH   24
#define HD   128
#define MLPD 12288
#define W1N  21504   // 3*HID + MLP
#define QKVN 9216    // 3*HID
#define CATN 15360   // HID + MLP

// ---------------- scratch (device globals; no allocations allowed) ----------
__device__ float  g_mod[3 * HID];
__device__ __half g_xmod[(size_t)LSEQ * HID];
__device__ __half g_h[(size_t)LSEQ * QKVN];          // qkv part only, fp16
__device__ __half g_q[(size_t)NH * LSEQ * HD];       // pre-scaled by D^-0.5
__device__ __half g_k[(size_t)NH * LSEQ * HD];
__device__ __half g_v[(size_t)NH * LSEQ * HD];
__device__ __half g_cat[(size_t)LSEQ * CATN];
__device__ __half g_w1h[(size_t)HID * W1N];
__device__ __half g_w2h[(size_t)CATN * HID];

// ---------------- async-copy / mma helpers -----------------------------------
__device__ __forceinline__ void cp16(unsigned dst, const void* src) {
    asm volatile("cp.async.cg.shared.global [%0], [%1], 16;\n" :: "r"(dst), "l"(src));
}
__device__ __forceinline__ void cp_commit() {
    asm volatile("cp.async.commit_group;\n");
}
__device__ __forceinline__ void cp_wait0() {
    asm volatile("cp.async.wait_group 0;\n");
}
__device__ __forceinline__ void cp_wait1() {
    asm volatile("cp.async.wait_group 1;\n");
}
__device__ __forceinline__ unsigned saddr(const void* p) {
    return (unsigned)__cvta_generic_to_shared(p);
}
__device__ __forceinline__ void ldsm4(uint32_t& r0, uint32_t& r1, uint32_t& r2,
                                      uint32_t& r3, unsigned addr) {
    asm volatile("ldmatrix.sync.aligned.m8n8.x4.shared.b16 {%0,%1,%2,%3}, [%4];"
                 : "=r"(r0), "=r"(r1), "=r"(r2), "=r"(r3) : "r"(addr));
}
__device__ __forceinline__ void ldsm4t(uint32_t& r0, uint32_t& r1, uint32_t& r2,
                                       uint32_t& r3, unsigned addr) {
    asm volatile("ldmatrix.sync.aligned.m8n8.x4.trans.shared.b16 {%0,%1,%2,%3}, [%4];"
                 : "=r"(r0), "=r"(r1), "=r"(r2), "=r"(r3) : "r"(addr));
}
__device__ __forceinline__ void mma16816(float* d, const uint32_t* a,
                                         uint32_t b0, uint32_t b1) {
    asm volatile(
        "mma.sync.aligned.m16n8k16.row.col.f32.f16.f16.f32 "
        "{%0,%1,%2,%3}, {%4,%5,%6,%7}, {%8,%9}, {%0,%1,%2,%3};\n"
        : "+f"(d[0]), "+f"(d[1]), "+f"(d[2]), "+f"(d[3])
        : "r"(a[0]), "r"(a[1]), "r"(a[2]), "r"(a[3]), "r"(b0), "r"(b1));
}
__device__ __forceinline__ uint32_t packh2(float x, float y) {
    __half2 h = __floats2half2_rn(x, y);
    return *reinterpret_cast<uint32_t*>(&h);
}

// ---------------- 0) fp32 -> fp16 weight conversion --------------------------
__global__ void k_convert_h(const float* __restrict__ in, __half* __restrict__ out,
                            size_t n8) {
    const float4* in4 = reinterpret_cast<const float4*>(in);
    uint4* out4 = reinterpret_cast<uint4*>(out);
    for (size_t i = (size_t)blockIdx.x * 256 + threadIdx.x; i < n8;
         i += (size_t)gridDim.x * 256) {
        float4 a = in4[2 * i], b = in4[2 * i + 1];
        __half2 h0 = __floats2half2_rn(a.x, a.y);
        __half2 h1 = __floats2half2_rn(a.z, a.w);
        __half2 h2 = __floats2half2_rn(b.x, b.y);
        __half2 h3 = __floats2half2_rn(b.z, b.w);
        uint4 o;
        o.x = *reinterpret_cast<unsigned*>(&h0);
        o.y = *reinterpret_cast<unsigned*>(&h1);
        o.z = *reinterpret_cast<unsigned*>(&h2);
        o.w = *reinterpret_cast<unsigned*>(&h3);
        out4[i] = o;
    }
}

// ---------------- 1) mod = silu(vec) @ mod_w + mod_b ------------------------
__global__ void k_mod_gemv(const float* __restrict__ vec,
                           const float* __restrict__ mw,
                           const float* __restrict__ mb) {
    __shared__ float sv[HID];
    int tid = threadIdx.x;
    for (int i = tid; i < HID; i += 256) {
        float v = vec[i];
        sv[i] = v / (1.f + expf(-v));
    }
    __syncthreads();
    int j = tid & 63, ky = tid >> 6;
    int col = blockIdx.x * 64 + j;
    const float* wp = mw + col;
    float acc = 0.f;
    int i0 = ky * 768;
#pragma unroll 4
    for (int i = i0; i < i0 + 768; ++i)
        acc += sv[i] * wp[(size_t)i * (3 * HID)];
    __shared__ float red[4][64];
    red[ky][j] = acc;
    __syncthreads();
    if (ky == 0)
        g_mod[col] = red[0][j] + red[1][j] + red[2][j] + red[3][j] + mb[col];
}

// ---------------- 2) LayerNorm + modulate (writes fp16) ----------------------
__global__ void k_ln_mod(const float* __restrict__ x,
                         const float* __restrict__ gamma,
                         const float* __restrict__ beta) {
    int l = blockIdx.x;
    const float* xr = x + (size_t)l * HID;
    float s = 0.f, ss = 0.f;
    for (int c = threadIdx.x; c < HID; c += 256) {
        float v = xr[c];
        s += v; ss += v * v;
    }
    __shared__ float rs[8], rss[8];
    for (int o = 16; o > 0; o >>= 1) {
        s  += __shfl_xor_sync(~0u, s, o);
        ss += __shfl_xor_sync(~0u, ss, o);
    }
    int w = threadIdx.x >> 5;
    if ((threadIdx.x & 31) == 0) { rs[w] = s; rss[w] = ss; }
    __syncthreads();
    float S = 0.f, SS = 0.f;
#pragma unroll
    for (int i = 0; i < 8; ++i) { S += rs[i]; SS += rss[i]; }
    float mu   = S * (1.f / HID);
    float var  = SS * (1.f / HID) - mu * mu;
    float rstd = rsqrtf(var + 1e-6f);
    __half* o = g_xmod + (size_t)l * HID;
    for (int c = threadIdx.x; c < HID; c += 256) {
        float ln = (xr[c] - mu) * rstd * gamma[c] + beta[c];
        o[c] = __float2half_rn((1.f + g_mod[HID + c]) * ln + g_mod[c]);
    }
}

// ---------------- FP16 GEMM: 128x128 CTA tile, BK=64, 3-stage ----------------
#define BM 128
#define BN 128
#define BK 64
#define NSTG 3
#define AS_H 72
#define BS_H 136
#define STG_A (BM * AS_H)
#define STG_B (BK * BS_H)
#define GEMM_DSMEM (NSTG * (STG_A + STG_B) * 2)

__global__ void __launch_bounds__(256, 2) k_gemm(
    const __half* __restrict__ A, int lda,
    const __half* __restrict__ B, int ldb, int K,
    const float* __restrict__ bias, int mode,
    float* __restrict__ f_out,
    const float* __restrict__ gate,
    const float* __restrict__ resid) {
    extern __shared__ __half hsm[];
    __shared__ float stage[8][16][16];

    int tid = threadIdx.x;
    int m0 = blockIdx.x * BM, n0 = blockIdx.y * BN;
    int w = tid >> 5, lane = tid & 31;
    int wm = w & 3, wn = w >> 2;   // warp tile 32x64

    int ar = tid >> 1, ac = (tid & 1) * 32;   // A: 2 thr/row, 32 halves each
    int br = tid >> 2, bc = (tid & 3) * 32;   // B: 4 thr/row, 32 halves each

    wmma::fragment<wmma::accumulator, 16, 16, 16, float> acc[2][4];
#pragma unroll
    for (int i = 0; i < 2; i++)
#pragma unroll
        for (int j = 0; j < 4; j++) wmma::fill_fragment(acc[i][j], 0.f);

    int nsteps = K / BK;
    auto issue = [&](int s) {
        int k0 = s * BK;
        __half* As = hsm + (s % NSTG) * (STG_A + STG_B);
        __half* Bs = As + STG_A;
        {
            const __half* src = A + (size_t)(m0 + ar) * lda + k0 + ac;
            unsigned dst = saddr(As + ar * AS_H + ac);
#pragma unroll
            for (int p = 0; p < 4; ++p) cp16(dst + p * 16, src + p * 8);
        }
        {
            const __half* src = B + (size_t)(k0 + br) * ldb + n0 + bc;
            unsigned dst = saddr(Bs + br * BS_H + bc);
#pragma unroll
            for (int p = 0; p < 4; ++p) cp16(dst + p * 16, src + p * 8);
        }
    };

    issue(0); cp_commit();
    issue(1); cp_commit();

    for (int s = 0; s < nsteps; ++s) {
        if (s + 1 < nsteps) cp_wait1(); else cp_wait0();
        __syncthreads();
        if (s + 2 < nsteps) { issue(s + 2); cp_commit(); }
        __half* As = hsm + (s % NSTG) * (STG_A + STG_B);
        __half* Bs = As + STG_A;
#pragma unroll
        for (int kt = 0; kt < 4; ++kt) {
            int kk = kt * 16;
            wmma::fragment<wmma::matrix_a, 16, 16, 16, __half, wmma::row_major> a[2];
            wmma::fragment<wmma::matrix_b, 16, 16, 16, __half, wmma::row_major> b[4];
#pragma unroll
            for (int i = 0; i < 2; i++)
                wmma::load_matrix_sync(a[i], As + (wm * 32 + i * 16) * AS_H + kk, AS_H);
#pragma unroll
            for (int j = 0; j < 4; j++)
                wmma::load_matrix_sync(b[j], Bs + kk * BS_H + wn * 64 + j * 16, BS_H);
#pragma unroll
            for (int i = 0; i < 2; i++)
#pragma unroll
                for (int j = 0; j < 4; j++)
                    wmma::mma_sync(acc[i][j], a[i], b[j], acc[i][j]);
        }
    }
    __syncthreads();

    bool isgelu = (mode == 0) && (n0 >= QKVN);
#pragma unroll
    for (int i = 0; i < 2; i++)
#pragma unroll
        for (int j = 0; j < 4; j++) {
            wmma::store_matrix_sync(&stage[w][0][0], acc[i][j], 16, wmma::mem_row_major);
            __syncwarp();
            for (int e = lane; e < 256; e += 32) {
                int r = e >> 4, c = e & 15;
                int gm = m0 + wm * 32 + i * 16 + r;
                int gn = n0 + wn * 64 + j * 16 + c;
                float val = stage[w][r][c] + bias[gn];
                if (mode == 0) {
                    if (!isgelu) {
                        g_h[(size_t)gm * QKVN + gn] = __float2half_rn(val);
                    } else {
                        float t = 0.7978845608028654f * (val + 0.044715f * val * val * val);
                        float g = 0.5f * val * (1.f + tanhf(t));
                        g_cat[(size_t)gm * CATN + HID + (gn - QKVN)] = __float2half_rn(g);
                    }
                } else {
                    f_out[(size_t)gm * HID + gn] =
                        resid[(size_t)gm * HID + gn] + gate[gn] * val;
                }
            }
            __syncwarp();
        }
}

// ---------------- 3) q/k rmsnorm + rope, v copy; [H][L][D] half --------------
__global__ void k_qkv(const float* __restrict__ pe,
                      const float* __restrict__ qs,
                      const float* __restrict__ ks) {
    int l = blockIdx.x, hh = blockIdx.y, d = threadIdx.x;
    const __half* hrow = g_h + (size_t)l * QKVN;
    float qv = __half2float(hrow[hh * HD + d]);
    float kv = __half2float(hrow[HID + hh * HD + d]);
    float vv = __half2float(hrow[2 * HID + hh * HD + d]);
    float sq = qv * qv, sk = kv * kv;
    for (int o = 16; o > 0; o >>= 1) {
        sq += __shfl_xor_sync(~0u, sq, o);
        sk += __shfl_xor_sync(~0u, sk, o);
    }
    __shared__ float wsq[4], wsk[4];
    int w = d >> 5;
    if ((d & 31) == 0) { wsq[w] = sq; wsk[w] = sk; }
    __syncthreads();
    float msq = (wsq[0] + wsq[1] + wsq[2] + wsq[3]) * (1.f / HD);
    float msk = (wsk[0] + wsk[1] + wsk[2] + wsk[3]) * (1.f / HD);
    __shared__ float nq[HD], nk[HD];
    nq[d] = qv * rsqrtf(msq + 1e-6f) * qs[d];
    nk[d] = kv * rsqrtf(msk + 1e-6f) * ks[d];
    __syncthreads();
    int c = d >> 1, r = d & 1;
    const float* pp = pe + ((size_t)l * 64 + c) * 4 + r * 2;
    float qr = pp[0] * nq[2 * c] + pp[1] * nq[2 * c + 1];
    float kr = pp[0] * nk[2 * c] + pp[1] * nk[2 * c + 1];
    size_t base = ((size_t)hh * LSEQ + l) * HD + d;
    g_q[base] = __float2half_rn(qr * 0.08838834764831845f);  // * D^-0.5
    g_k[base] = __float2half_rn(kr);
    g_v[base] = __float2half_rn(vv);
}

// ---------------- 4) flash attention: 64 q rows/CTA, 4 warps, online softmax -
#define KS_H 136                       // halves per K/V tile row
#define FA_BUF (64 * KS_H)             // one tile buffer (halves)
#define FA_NSTG 3
#define FA_DSMEM (FA_NSTG * 2 * FA_BUF * 2)
#define NKT (LSEQ / 64)                // 32 kv tiles

__global__ void __launch_bounds__(128, 2) k_fattn() {
    extern __shared__ __half fsm[];
    int tid = threadIdx.x, w = tid >> 5, lane = tid & 31;
    int hh = blockIdx.y;
    int q0 = blockIdx.x * 64;
    const __half* Qg = g_q + ((size_t)hh * LSEQ + q0 + w * 16) * HD;
    const __half* Kg = g_k + (size_t)hh * LSEQ * HD;
    const __half* Vg = g_v + (size_t)hh * LSEQ * HD;

    // Q a-fragments (m16n8k16 A layout), 8 k-chunks of 16
    int fr = lane >> 2;          // 0..7 (row within half-tile)
    int fc = (lane & 3) * 2;     // 0,2,4,6
    uint32_t qa[8][4];
#pragma unroll
    for (int kc = 0; kc < 8; ++kc) {
        qa[kc][0] = *reinterpret_cast<const uint32_t*>(&Qg[(size_t)fr * HD + kc * 16 + fc]);
        qa[kc][1] = *reinterpret_cast<const uint32_t*>(&Qg[(size_t)(fr + 8) * HD + kc * 16 + fc]);
        qa[kc][2] = *reinterpret_cast<const uint32_t*>(&Qg[(size_t)fr * HD + kc * 16 + 8 + fc]);
        qa[kc][3] = *reinterpret_cast<const uint32_t*>(&Qg[(size_t)(fr + 8) * HD + kc * 16 + 8 + fc]);
    }

    float o[16][4];
#pragma unroll
    for (int c = 0; c < 16; ++c)
#pragma unroll
        for (int j = 0; j < 4; ++j) o[c][j] = 0.f;
    float m0 = -1e30f, m1 = -1e30f, l0 = 0.f, l1 = 0.f;

    int sr = tid >> 1, sc = (tid & 1) * 64;   // stage slot: 2 thr/row, 64 halves
    auto stg = [&](int t) {
        __half* Ks = fsm + (t % FA_NSTG) * 2 * FA_BUF;
        __half* Vs = Ks + FA_BUF;
        const __half* ksrc = Kg + (size_t)(t * 64 + sr) * HD + sc;
        unsigned kd = saddr(Ks + sr * KS_H + sc);
#pragma unroll
        for (int p = 0; p < 8; ++p) cp16(kd + p * 16, ksrc + p * 8);
        const __half* vsrc = Vg + (size_t)(t * 64 + sr) * HD + sc;
        unsigned vd = saddr(Vs + sr * KS_H + sc);
#pragma unroll
        for (int p = 0; p < 8; ++p) cp16(vd + p * 16, vsrc + p * 8);
    };

    stg(0); cp_commit();
    stg(1); cp_commit();

    int lm = lane >> 3, lr = lane & 7;   // ldmatrix lane -> (matrix, row)

    for (int t = 0; t < NKT; ++t) {
        if (t + 1 < NKT) cp_wait1(); else cp_wait0();
        __syncthreads();
        if (t + 2 < NKT) { stg(t + 2); cp_commit(); }
        __half* Ks = fsm + (t % FA_NSTG) * 2 * FA_BUF;
        __half* Vs = Ks + FA_BUF;
        unsigned kbase = saddr(Ks), vbase = saddr(Vs);

        // ---- S = Q @ K^T  (16 x 64), 8 n8-chunks
        float s[8][4];
#pragma unroll
        for (int c = 0; c < 8; ++c)
#pragma unroll
            for (int j = 0; j < 4; ++j) s[c][j] = 0.f;
#pragma unroll
        for (int kc = 0; kc < 8; ++kc) {
#pragma unroll
            for (int cp = 0; cp < 4; ++cp) {
                // non-trans: m0/m1 = chunk 2cp (k lo/hi), m2/m3 = chunk 2cp+1
                unsigned addr = kbase +
                    (((2 * cp + (lm >> 1)) * 8 + lr) * KS_H + kc * 16 + (lm & 1) * 8) * 2;
                uint32_t b0, b1, b2, b3;
                ldsm4(b0, b1, b2, b3, addr);
                mma16816(s[2 * cp], qa[kc], b0, b1);
                mma16816(s[2 * cp + 1], qa[kc], b2, b3);
            }
        }

        // ---- online softmax (rows fr and fr+8)
        float t0 = -1e30f, t1 = -1e30f;
#pragma unroll
        for (int c = 0; c < 8; ++c) {
            t0 = fmaxf(t0, fmaxf(s[c][0], s[c][1]));
            t1 = fmaxf(t1, fmaxf(s[c][2], s[c][3]));
        }
        t0 = fmaxf(t0, __shfl_xor_sync(~0u, t0, 1));
        t0 = fmaxf(t0, __shfl_xor_sync(~0u, t0, 2));
        t1 = fmaxf(t1, __shfl_xor_sync(~0u, t1, 1));
        t1 = fmaxf(t1, __shfl_xor_sync(~0u, t1, 2));
        float mn0 = fmaxf(m0, t0), mn1 = fmaxf(m1, t1);
        float sc0 = __expf(m0 - mn0), sc1 = __expf(m1 - mn1);
        m0 = mn0; m1 = mn1;
        uint32_t ph[8][2];
        float ps0 = 0.f, ps1 = 0.f;
#pragma unroll
        for (int c = 0; c < 8; ++c) {
            float e0 = __expf(s[c][0] - mn0);
            float e1 = __expf(s[c][1] - mn0);
            float e2 = __expf(s[c][2] - mn1);
            float e3 = __expf(s[c][3] - mn1);
            ps0 += e0 + e1; ps1 += e2 + e3;
            ph[c][0] = packh2(e0, e1);
            ph[c][1] = packh2(e2, e3);
        }
        l0 = l0 * sc0 + ps0;
        l1 = l1 * sc1 + ps1;
#pragma unroll
        for (int c = 0; c < 16; ++c) {
            o[c][0] *= sc0; o[c][1] *= sc0;
            o[c][2] *= sc1; o[c][3] *= sc1;
        }

        // ---- O += P @ V  (16 x 128), 4 kv k-chunks of 16
#pragma unroll
        for (int kg = 0; kg < 4; ++kg) {
            uint32_t pa[4] = {ph[2 * kg][0], ph[2 * kg][1],
                              ph[2 * kg + 1][0], ph[2 * kg + 1][1]};
#pragma unroll
            for (int cp = 0; cp < 8; ++cp) {
                // trans: m0/m1 = hd chunk 2cp (k lo/hi), m2/m3 = chunk 2cp+1
                unsigned addr = vbase +
                    ((kg * 16 + (lm & 1) * 8 + lr) * KS_H + (2 * cp + (lm >> 1)) * 8) * 2;
                uint32_t b0, b1, b2, b3;
                ldsm4t(b0, b1, b2, b3, addr);
                mma16816(o[2 * cp], pa, b0, b1);
                mma16816(o[2 * cp + 1], pa, b2, b3);
            }
        }
    }

    // final: normalize and store
    l0 += __shfl_xor_sync(~0u, l0, 1);
    l0 += __shfl_xor_sync(~0u, l0, 2);
    l1 += __shfl_xor_sync(~0u, l1, 1);
    l1 += __shfl_xor_sync(~0u, l1, 2);
    float il0 = 1.f / l0, il1 = 1.f / l1;
    int row0 = q0 + w * 16 + fr;
    int row1 = row0 + 8;
#pragma unroll
    for (int c = 0; c < 16; ++c) {
        int col = hh * HD + c * 8 + fc;
        *reinterpret_cast<uint32_t*>(&g_cat[(size_t)row0 * CATN + col]) =
            packh2(o[c][0] * il0, o[c][1] * il0);
        *reinterpret_cast<uint32_t*>(&g_cat[(size_t)row1 * CATN + col]) =
            packh2(o[c][2] * il1, o[c][3] * il1);
    }
}

// ---------------- launch -----------------------------------------------------
extern "C" void kernel_launch(void* const* d_in, const int* in_sizes, int n_in,
                              void* d_out, int out_size) {
    const float* x     = (const float*)d_in[0];
    const float* vec   = (const float*)d_in[1];
    const float* pe    = (const float*)d_in[2];
    const float* mod_w = (const float*)d_in[3];
    const float* mod_b = (const float*)d_in[4];
    const float* ln_g  = (const float*)d_in[5];
    const float* ln_b  = (const float*)d_in[6];
    const float* w1    = (const float*)d_in[7];
    const float* b1    = (const float*)d_in[8];
    const float* q_s   = (const float*)d_in[9];
    const float* k_s   = (const float*)d_in[10];
    const float* w2    = (const float*)d_in[11];
    const float* b2    = (const float*)d_in[12];
    float* out = (float*)d_out;

    __half *p_xmod, *p_cat, *p_w1h, *p_w2h;
    float *p_mod;
    cudaGetSymbolAddress((void**)&p_xmod, g_xmod);
    cudaGetSymbolAddress((void**)&p_cat,  g_cat);
    cudaGetSymbolAddress((void**)&p_mod,  g_mod);
    cudaGetSymbolAddress((void**)&p_w1h,  g_w1h);
    cudaGetSymbolAddress((void**)&p_w2h,  g_w2h);

    cudaFuncSetAttribute(k_fattn, cudaFuncAttributeMaxDynamicSharedMemorySize,
                         FA_DSMEM);
    cudaFuncSetAttribute(k_gemm, cudaFuncAttributeMaxDynamicSharedMemorySize,
                         GEMM_DSMEM);

    k_mod_gemv<<<144, 256>>>(vec, mod_w, mod_b);                       // 1
    k_convert_h<<<4096, 256>>>(w1, p_w1h, (size_t)HID * W1N / 8);      // 2
    k_ln_mod<<<LSEQ, 256>>>(x, ln_g, ln_b);                            // 3
    // h|gelu(mlp) = x_mod @ w1 + b1       (launch #4 -> profiled)
    k_gemm<<<dim3(16, 168), 256, GEMM_DSMEM>>>(p_xmod, HID, p_w1h, W1N,
                                               HID, b1, 0,
                                               nullptr, nullptr, nullptr);
    k_qkv<<<dim3(LSEQ, NH), 128>>>(pe, q_s, k_s);                      // 5
    k_fattn<<<dim3(LSEQ / 64, NH), 128, FA_DSMEM>>>();                 // 6
    k_convert_h<<<4096, 256>>>(w2, p_w2h, (size_t)CATN * HID / 8);     // 7
    // out = x + gate * (cat @ w2 + b2)
    k_gemm<<<dim3(16, 24), 256, GEMM_DSMEM>>>(p_cat, CATN, p_w2h, HID,
                                              CATN, b2, 1,
                                              out, p_mod + 2 * HID, x);
    (void)in_sizes; (void)n_in; (void)out_size;
}

// round 10
// speedup vs baseline: 5.1385x; 1.2237x over previous
#include <cuda_runtime.h>
#include <cstdint>
#include <stdint.h>
#include <cuda_fp16.h>
#include <mma.h>
#include <math.h>

using namespace nvcuda;

#define LSEQ 2048
#define HID  3072
#define NH   24
#define HD   128
#define MLPD 12288
#define W1N  21504   // 3*HID + MLP
#define QKVN 9216    // 3*HID
#define CATN 15360   // HID + MLP

// ---------------- scratch (device globals; no allocations allowed) ----------
__device__ float  g_mod[3 * HID];
__device__ __half g_xmod[(size_t)LSEQ * HID];
__device__ __half g_h[(size_t)LSEQ * QKVN];          // qkv part only, fp16
__device__ __half g_q[(size_t)NH * LSEQ * HD];       // pre-scaled by D^-0.5
__device__ __half g_k[(size_t)NH * LSEQ * HD];
__device__ __half g_v[(size_t)NH * LSEQ * HD];
__device__ __half g_cat[(size_t)LSEQ * CATN];
__device__ __half g_w1h[(size_t)HID * W1N];
__device__ __half g_w2h[(size_t)CATN * HID];

// ---------------- async-copy / mma helpers -----------------------------------
__device__ __forceinline__ void cp16(unsigned dst, const void* src) {
    asm volatile("cp.async.cg.shared.global [%0], [%1], 16;\n" :: "r"(dst), "l"(src));
}
__device__ __forceinline__ void cp_commit() {
    asm volatile("cp.async.commit_group;\n");
}
__device__ __forceinline__ void cp_wait0() {
    asm volatile("cp.async.wait_group 0;\n");
}
__device__ __forceinline__ void cp_wait1() {
    asm volatile("cp.async.wait_group 1;\n");
}
__device__ __forceinline__ unsigned saddr(const void* p) {
    return (unsigned)__cvta_generic_to_shared(p);
}
__device__ __forceinline__ void ldsm4(uint32_t& r0, uint32_t& r1, uint32_t& r2,
                                      uint32_t& r3, unsigned addr) {
    asm volatile("ldmatrix.sync.aligned.m8n8.x4.shared.b16 {%0,%1,%2,%3}, [%4];"
                 : "=r"(r0), "=r"(r1), "=r"(r2), "=r"(r3) : "r"(addr));
}
__device__ __forceinline__ void ldsm4t(uint32_t& r0, uint32_t& r1, uint32_t& r2,
                                       uint32_t& r3, unsigned addr) {
    asm volatile("ldmatrix.sync.aligned.m8n8.x4.trans.shared.b16 {%0,%1,%2,%3}, [%4];"
                 : "=r"(r0), "=r"(r1), "=r"(r2), "=r"(r3) : "r"(addr));
}
__device__ __forceinline__ void mma16816(float* d, const uint32_t* a,
                                         uint32_t b0, uint32_t b1) {
    asm volatile(
        "mma.sync.aligned.m16n8k16.row.col.f32.f16.f16.f32 "
        "{%0,%1,%2,%3}, {%4,%5,%6,%7}, {%8,%9}, {%0,%1,%2,%3};\n"
        : "+f"(d[0]), "+f"(d[1]), "+f"(d[2]), "+f"(d[3])
        : "r"(a[0]), "r"(a[1]), "r"(a[2]), "r"(a[3]), "r"(b0), "r"(b1));
}
__device__ __forceinline__ uint32_t packh2(float x, float y) {
    __half2 h = __floats2half2_rn(x, y);
    return *reinterpret_cast<uint32_t*>(&h);
}

// ---------------- 0) fp32 -> fp16 weight conversion --------------------------
__global__ void k_convert_h(const float* __restrict__ in, __half* __restrict__ out,
                            size_t n8) {
    const float4* in4 = reinterpret_cast<const float4*>(in);
    uint4* out4 = reinterpret_cast<uint4*>(out);
    for (size_t i = (size_t)blockIdx.x * 256 + threadIdx.x; i < n8;
         i += (size_t)gridDim.x * 256) {
        float4 a = in4[2 * i], b = in4[2 * i + 1];
        __half2 h0 = __floats2half2_rn(a.x, a.y);
        __half2 h1 = __floats2half2_rn(a.z, a.w);
        __half2 h2 = __floats2half2_rn(b.x, b.y);
        __half2 h3 = __floats2half2_rn(b.z, b.w);
        uint4 o;
        o.x = *reinterpret_cast<unsigned*>(&h0);
        o.y = *reinterpret_cast<unsigned*>(&h1);
        o.z = *reinterpret_cast<unsigned*>(&h2);
        o.w = *reinterpret_cast<unsigned*>(&h3);
        out4[i] = o;
    }
}

// ---------------- 1) mod = silu(vec) @ mod_w + mod_b ------------------------
__global__ void k_mod_gemv(const float* __restrict__ vec,
                           const float* __restrict__ mw,
                           const float* __restrict__ mb) {
    __shared__ float sv[HID];
    int tid = threadIdx.x;
    for (int i = tid; i < HID; i += 256) {
        float v = vec[i];
        sv[i] = v / (1.f + expf(-v));
    }
    __syncthreads();
    int j = tid & 63, ky = tid >> 6;
    int col = blockIdx.x * 64 + j;
    const float* wp = mw + col;
    float acc = 0.f;
    int i0 = ky * 768;
#pragma unroll 4
    for (int i = i0; i < i0 + 768; ++i)
        acc += sv[i] * wp[(size_t)i * (3 * HID)];
    __shared__ float red[4][64];
    red[ky][j] = acc;
    __syncthreads();
    if (ky == 0)
        g_mod[col] = red[0][j] + red[1][j] + red[2][j] + red[3][j] + mb[col];
}

// ---------------- 2) LayerNorm + modulate (writes fp16) ----------------------
__global__ void k_ln_mod(const float* __restrict__ x,
                         const float* __restrict__ gamma,
                         const float* __restrict__ beta) {
    int l = blockIdx.x;
    const float* xr = x + (size_t)l * HID;
    float s = 0.f, ss = 0.f;
    for (int c = threadIdx.x; c < HID; c += 256) {
        float v = xr[c];
        s += v; ss += v * v;
    }
    __shared__ float rs[8], rss[8];
    for (int o = 16; o > 0; o >>= 1) {
        s  += __shfl_xor_sync(~0u, s, o);
        ss += __shfl_xor_sync(~0u, ss, o);
    }
    int w = threadIdx.x >> 5;
    if ((threadIdx.x & 31) == 0) { rs[w] = s; rss[w] = ss; }
    __syncthreads();
    float S = 0.f, SS = 0.f;
#pragma unroll
    for (int i = 0; i < 8; ++i) { S += rs[i]; SS += rss[i]; }
    float mu   = S * (1.f / HID);
    float var  = SS * (1.f / HID) - mu * mu;
    float rstd = rsqrtf(var + 1e-6f);
    __half* o = g_xmod + (size_t)l * HID;
    for (int c = threadIdx.x; c < HID; c += 256) {
        float ln = (xr[c] - mu) * rstd * gamma[c] + beta[c];
        o[c] = __float2half_rn((1.f + g_mod[HID + c]) * ln + g_mod[c]);
    }
}

// ---------------- FP16 GEMM: 128x128 CTA tile, BK=32, 3-stage (R8 config) ----
#define BM 128
#define BN 128
#define BK 32
#define NSTG 3
#define AS_H 40
#define BS_H 136
#define STG_A (BM * AS_H)
#define STG_B (BK * BS_H)
#define GEMM_DSMEM (NSTG * (STG_A + STG_B) * 2)

__global__ void __launch_bounds__(256, 2) k_gemm(
    const __half* __restrict__ A, int lda,
    const __half* __restrict__ B, int ldb, int K,
    const float* __restrict__ bias, int mode,
    float* __restrict__ f_out,
    const float* __restrict__ gate,
    const float* __restrict__ resid) {
    extern __shared__ __half hsm[];
    __shared__ float stage[8][16][16];

    int tid = threadIdx.x;
    int m0 = blockIdx.x * BM, n0 = blockIdx.y * BN;
    int w = tid >> 5, lane = tid & 31;
    int wm = w & 3, wn = w >> 2;   // warp tile 32x64

    int ar = tid >> 1, ac = (tid & 1) * 16;   // A: 2 thr/row, 16 halves each
    int br = tid >> 3, bc = (tid & 7) * 16;   // B: 8 thr/row, 16 halves each

    wmma::fragment<wmma::accumulator, 16, 16, 16, float> acc[2][4];
#pragma unroll
    for (int i = 0; i < 2; i++)
#pragma unroll
        for (int j = 0; j < 4; j++) wmma::fill_fragment(acc[i][j], 0.f);

    int nsteps = K / BK;
    auto issue = [&](int s) {
        int k0 = s * BK;
        __half* As = hsm + (s % NSTG) * (STG_A + STG_B);
        __half* Bs = As + STG_A;
        {
            const __half* src = A + (size_t)(m0 + ar) * lda + k0 + ac;
            unsigned dst = saddr(As + ar * AS_H + ac);
            cp16(dst, src);
            cp16(dst + 16, src + 8);
        }
        {
            const __half* src = B + (size_t)(k0 + br) * ldb + n0 + bc;
            unsigned dst = saddr(Bs + br * BS_H + bc);
            cp16(dst, src);
            cp16(dst + 16, src + 8);
        }
    };

    issue(0); cp_commit();
    issue(1); cp_commit();

    for (int s = 0; s < nsteps; ++s) {
        if (s + 1 < nsteps) cp_wait1(); else cp_wait0();
        __syncthreads();
        if (s + 2 < nsteps) { issue(s + 2); cp_commit(); }
        __half* As = hsm + (s % NSTG) * (STG_A + STG_B);
        __half* Bs = As + STG_A;
#pragma unroll
        for (int kt = 0; kt < 2; ++kt) {
            int kk = kt * 16;
            wmma::fragment<wmma::matrix_a, 16, 16, 16, __half, wmma::row_major> a[2];
            wmma::fragment<wmma::matrix_b, 16, 16, 16, __half, wmma::row_major> b[4];
#pragma unroll
            for (int i = 0; i < 2; i++)
                wmma::load_matrix_sync(a[i], As + (wm * 32 + i * 16) * AS_H + kk, AS_H);
#pragma unroll
            for (int j = 0; j < 4; j++)
                wmma::load_matrix_sync(b[j], Bs + kk * BS_H + wn * 64 + j * 16, BS_H);
#pragma unroll
            for (int i = 0; i < 2; i++)
#pragma unroll
                for (int j = 0; j < 4; j++)
                    wmma::mma_sync(acc[i][j], a[i], b[j], acc[i][j]);
        }
    }
    __syncthreads();

    bool isgelu = (mode == 0) && (n0 >= QKVN);
#pragma unroll
    for (int i = 0; i < 2; i++)
#pragma unroll
        for (int j = 0; j < 4; j++) {
            wmma::store_matrix_sync(&stage[w][0][0], acc[i][j], 16, wmma::mem_row_major);
            __syncwarp();
            for (int e = lane; e < 256; e += 32) {
                int r = e >> 4, c = e & 15;
                int gm = m0 + wm * 32 + i * 16 + r;
                int gn = n0 + wn * 64 + j * 16 + c;
                float val = stage[w][r][c] + bias[gn];
                if (mode == 0) {
                    if (!isgelu) {
                        g_h[(size_t)gm * QKVN + gn] = __float2half_rn(val);
                    } else {
                        float t = 0.7978845608028654f * (val + 0.044715f * val * val * val);
                        float g = 0.5f * val * (1.f + tanhf(t));
                        g_cat[(size_t)gm * CATN + HID + (gn - QKVN)] = __float2half_rn(g);
                    }
                } else {
                    f_out[(size_t)gm * HID + gn] =
                        resid[(size_t)gm * HID + gn] + gate[gn] * val;
                }
            }
            __syncwarp();
        }
}

// ---------------- 3) q/k rmsnorm + rope, v copy; [H][L][D] half --------------
__global__ void k_qkv(const float* __restrict__ pe,
                      const float* __restrict__ qs,
                      const float* __restrict__ ks) {
    int l = blockIdx.x, hh = blockIdx.y, d = threadIdx.x;
    const __half* hrow = g_h + (size_t)l * QKVN;
    float qv = __half2float(hrow[hh * HD + d]);
    float kv = __half2float(hrow[HID + hh * HD + d]);
    float vv = __half2float(hrow[2 * HID + hh * HD + d]);
    float sq = qv * qv, sk = kv * kv;
    for (int o = 16; o > 0; o >>= 1) {
        sq += __shfl_xor_sync(~0u, sq, o);
        sk += __shfl_xor_sync(~0u, sk, o);
    }
    __shared__ float wsq[4], wsk[4];
    int w = d >> 5;
    if ((d & 31) == 0) { wsq[w] = sq; wsk[w] = sk; }
    __syncthreads();
    float msq = (wsq[0] + wsq[1] + wsq[2] + wsq[3]) * (1.f / HD);
    float msk = (wsk[0] + wsk[1] + wsk[2] + wsk[3]) * (1.f / HD);
    __shared__ float nq[HD], nk[HD];
    nq[d] = qv * rsqrtf(msq + 1e-6f) * qs[d];
    nk[d] = kv * rsqrtf(msk + 1e-6f) * ks[d];
    __syncthreads();
    int c = d >> 1, r = d & 1;
    const float* pp = pe + ((size_t)l * 64 + c) * 4 + r * 2;
    float qr = pp[0] * nq[2 * c] + pp[1] * nq[2 * c + 1];
    float kr = pp[0] * nk[2 * c] + pp[1] * nk[2 * c + 1];
    size_t base = ((size_t)hh * LSEQ + l) * HD + d;
    g_q[base] = __float2half_rn(qr * 0.08838834764831845f);  // * D^-0.5
    g_k[base] = __float2half_rn(kr);
    g_v[base] = __float2half_rn(vv);
}

// ---------------- 4) flash attention: 128 q rows/CTA, 8 warps ----------------
#define KS_H 136                       // halves per K/V tile row
#define FA_BUF (64 * KS_H)             // one tile buffer (halves)
#define FA_NSTG 3
#define FA_DSMEM (FA_NSTG * 2 * FA_BUF * 2)
#define NKT (LSEQ / 64)                // 32 kv tiles

__global__ void __launch_bounds__(256, 1) k_fattn() {
    extern __shared__ __half fsm[];
    int tid = threadIdx.x, w = tid >> 5, lane = tid & 31;
    int hh = blockIdx.y;
    int q0 = blockIdx.x * 128;
    const __half* Qg = g_q + ((size_t)hh * LSEQ + q0 + w * 16) * HD;
    const __half* Kg = g_k + (size_t)hh * LSEQ * HD;
    const __half* Vg = g_v + (size_t)hh * LSEQ * HD;

    // Q a-fragments (m16n8k16 A layout), 8 k-chunks of 16
    int fr = lane >> 2;          // 0..7 (row within half-tile)
    int fc = (lane & 3) * 2;     // 0,2,4,6
    uint32_t qa[8][4];
#pragma unroll
    for (int kc = 0; kc < 8; ++kc) {
        qa[kc][0] = *reinterpret_cast<const uint32_t*>(&Qg[(size_t)fr * HD + kc * 16 + fc]);
        qa[kc][1] = *reinterpret_cast<const uint32_t*>(&Qg[(size_t)(fr + 8) * HD + kc * 16 + fc]);
        qa[kc][2] = *reinterpret_cast<const uint32_t*>(&Qg[(size_t)fr * HD + kc * 16 + 8 + fc]);
        qa[kc][3] = *reinterpret_cast<const uint32_t*>(&Qg[(size_t)(fr + 8) * HD + kc * 16 + 8 + fc]);
    }

    float o[16][4];
#pragma unroll
    for (int c = 0; c < 16; ++c)
#pragma unroll
        for (int j = 0; j < 4; ++j) o[c][j] = 0.f;
    float m0 = -1e30f, m1 = -1e30f, l0 = 0.f, l1 = 0.f;

    // stage slots: 256 threads, 64 rows -> 4 thr/row, 32 halves each
    int sr = tid >> 2, sc = (tid & 3) * 32;
    auto stg = [&](int t) {
        __half* Ks = fsm + (t % FA_NSTG) * 2 * FA_BUF;
        __half* Vs = Ks + FA_BUF;
        const __half* ksrc = Kg + (size_t)(t * 64 + sr) * HD + sc;
        unsigned kd = saddr(Ks + sr * KS_H + sc);
#pragma unroll
        for (int p = 0; p < 4; ++p) cp16(kd + p * 16, ksrc + p * 8);
        const __half* vsrc = Vg + (size_t)(t * 64 + sr) * HD + sc;
        unsigned vd = saddr(Vs + sr * KS_H + sc);
#pragma unroll
        for (int p = 0; p < 4; ++p) cp16(vd + p * 16, vsrc + p * 8);
    };

    stg(0); cp_commit();
    stg(1); cp_commit();

    int lm = lane >> 3, lr = lane & 7;   // ldmatrix lane -> (matrix, row)

    for (int t = 0; t < NKT; ++t) {
        if (t + 1 < NKT) cp_wait1(); else cp_wait0();
        __syncthreads();
        if (t + 2 < NKT) { stg(t + 2); cp_commit(); }
        __half* Ks = fsm + (t % FA_NSTG) * 2 * FA_BUF;
        __half* Vs = Ks + FA_BUF;
        unsigned kbase = saddr(Ks), vbase = saddr(Vs);

        // ---- S = Q @ K^T  (16 x 64), 8 n8-chunks
        float s[8][4];
#pragma unroll
        for (int c = 0; c < 8; ++c)
#pragma unroll
            for (int j = 0; j < 4; ++j) s[c][j] = 0.f;
#pragma unroll
        for (int kc = 0; kc < 8; ++kc) {
#pragma unroll
            for (int cp = 0; cp < 4; ++cp) {
                unsigned addr = kbase +
                    (((2 * cp + (lm >> 1)) * 8 + lr) * KS_H + kc * 16 + (lm & 1) * 8) * 2;
                uint32_t b0, b1, b2, b3;
                ldsm4(b0, b1, b2, b3, addr);
                mma16816(s[2 * cp], qa[kc], b0, b1);
                mma16816(s[2 * cp + 1], qa[kc], b2, b3);
            }
        }

        // ---- online softmax (rows fr and fr+8)
        float t0 = -1e30f, t1 = -1e30f;
#pragma unroll
        for (int c = 0; c < 8; ++c) {
            t0 = fmaxf(t0, fmaxf(s[c][0], s[c][1]));
            t1 = fmaxf(t1, fmaxf(s[c][2], s[c][3]));
        }
        t0 = fmaxf(t0, __shfl_xor_sync(~0u, t0, 1));
        t0 = fmaxf(t0, __shfl_xor_sync(~0u, t0, 2));
        t1 = fmaxf(t1, __shfl_xor_sync(~0u, t1, 1));
        t1 = fmaxf(t1, __shfl_xor_sync(~0u, t1, 2));
        float mn0 = fmaxf(m0, t0), mn1 = fmaxf(m1, t1);
        float sc0 = __expf(m0 - mn0), sc1 = __expf(m1 - mn1);
        m0 = mn0; m1 = mn1;
        uint32_t ph[8][2];
        float ps0 = 0.f, ps1 = 0.f;
#pragma unroll
        for (int c = 0; c < 8; ++c) {
            float e0 = __expf(s[c][0] - mn0);
            float e1 = __expf(s[c][1] - mn0);
            float e2 = __expf(s[c][2] - mn1);
            float e3 = __expf(s[c][3] - mn1);
            ps0 += e0 + e1; ps1 += e2 + e3;
            ph[c][0] = packh2(e0, e1);
            ph[c][1] = packh2(e2, e3);
        }
        l0 = l0 * sc0 + ps0;
        l1 = l1 * sc1 + ps1;
#pragma unroll
        for (int c = 0; c < 16; ++c) {
            o[c][0] *= sc0; o[c][1] *= sc0;
            o[c][2] *= sc1; o[c][3] *= sc1;
        }

        // ---- O += P @ V  (16 x 128), 4 kv k-chunks of 16
#pragma unroll
        for (int kg = 0; kg < 4; ++kg) {
            uint32_t pa[4] = {ph[2 * kg][0], ph[2 * kg][1],
                              ph[2 * kg + 1][0], ph[2 * kg + 1][1]};
#pragma unroll
            for (int cp = 0; cp < 8; ++cp) {
                unsigned addr = vbase +
                    ((kg * 16 + (lm & 1) * 8 + lr) * KS_H + (2 * cp + (lm >> 1)) * 8) * 2;
                uint32_t b0, b1, b2, b3;
                ldsm4t(b0, b1, b2, b3, addr);
                mma16816(o[2 * cp], pa, b0, b1);
                mma16816(o[2 * cp + 1], pa, b2, b3);
            }
        }
    }

    // final: normalize and store
    l0 += __shfl_xor_sync(~0u, l0, 1);
    l0 += __shfl_xor_sync(~0u, l0, 2);
    l1 += __shfl_xor_sync(~0u, l1, 1);
    l1 += __shfl_xor_sync(~0u, l1, 2);
    float il0 = 1.f / l0, il1 = 1.f / l1;
    int row0 = q0 + w * 16 + fr;
    int row1 = row0 + 8;
#pragma unroll
    for (int c = 0; c < 16; ++c) {
        int col = hh * HD + c * 8 + fc;
        *reinterpret_cast<uint32_t*>(&g_cat[(size_t)row0 * CATN + col]) =
            packh2(o[c][0] * il0, o[c][1] * il0);
        *reinterpret_cast<uint32_t*>(&g_cat[(size_t)row1 * CATN + col]) =
            packh2(o[c][2] * il1, o[c][3] * il1);
    }
}

// ---------------- launch -----------------------------------------------------
extern "C" void kernel_launch(void* const* d_in, const int* in_sizes, int n_in,
                              void* d_out, int out_size) {
    const float* x     = (const float*)d_in[0];
    const float* vec   = (const float*)d_in[1];
    const float* pe    = (const float*)d_in[2];
    const float* mod_w = (const float*)d_in[3];
    const float* mod_b = (const float*)d_in[4];
    const float* ln_g  = (const float*)d_in[5];
    const float* ln_b  = (const float*)d_in[6];
    const float* w1    = (const float*)d_in[7];
    const float* b1    = (const float*)d_in[8];
    const float* q_s   = (const float*)d_in[9];
    const float* k_s   = (const float*)d_in[10];
    const float* w2    = (const float*)d_in[11];
    const float* b2    = (const float*)d_in[12];
    float* out = (float*)d_out;

    __half *p_xmod, *p_cat, *p_w1h, *p_w2h;
    float *p_mod;
    cudaGetSymbolAddress((void**)&p_xmod, g_xmod);
    cudaGetSymbolAddress((void**)&p_cat,  g_cat);
    cudaGetSymbolAddress((void**)&p_mod,  g_mod);
    cudaGetSymbolAddress((void**)&p_w1h,  g_w1h);
    cudaGetSymbolAddress((void**)&p_w2h,  g_w2h);

    cudaFuncSetAttribute(k_fattn, cudaFuncAttributeMaxDynamicSharedMemorySize,
                         FA_DSMEM);
    cudaFuncSetAttribute(k_gemm, cudaFuncAttributeMaxDynamicSharedMemorySize,
                         GEMM_DSMEM);

    k_mod_gemv<<<144, 256>>>(vec, mod_w, mod_b);                       // 1
    k_convert_h<<<4096, 256>>>(w1, p_w1h, (size_t)HID * W1N / 8);      // 2
    k_ln_mod<<<LSEQ, 256>>>(x, ln_g, ln_b);                            // 3
    // h|gelu(mlp) = x_mod @ w1 + b1       (launch #4 -> profiled)
    k_gemm<<<dim3(16, 168), 256, GEMM_DSMEM>>>(p_xmod, HID, p_w1h, W1N,
                                               HID, b1, 0,
                                               nullptr, nullptr, nullptr);
    k_qkv<<<dim3(LSEQ, NH), 128>>>(pe, q_s, k_s);                      // 5
    k_fattn<<<dim3(LSEQ / 128, NH), 256, FA_DSMEM>>>();                // 6
    k_convert_h<<<4096, 256>>>(w2, p_w2h, (size_t)CATN * HID / 8);     // 7
    // out = x + gate * (cat @ w2 + b2)
    k_gemm<<<dim3(16, 24), 256, GEMM_DSMEM>>>(p_cat, CATN, p_w2h, HID,
                                              CATN, b2, 1,
                                              out, p_mod + 2 * HID, x);
    (void)in_sizes; (void)n_in; (void)out_size;
}

// round 11
// speedup vs baseline: 5.1795x; 1.0080x over previous
#include <cuda_runtime.h>
#include <cstdint>
#include <stdint.h>
#include <cuda_fp16.h>
#include <mma.h>
#include <math.h>

#define LSEQ 2048
#define HID  3072
#define NH   24
#define HD   128
#define MLPD 12288
#define W1N  21504   // 3*HID + MLP
#define QKVN 9216    // 3*HID
#define CATN 15360   // HID + MLP

// ---------------- scratch (device globals; no allocations allowed) ----------
__device__ float  g_mod[3 * HID];
__device__ __half g_xmod[(size_t)LSEQ * HID];
__device__ __half g_h[(size_t)LSEQ * QKVN];          // qkv part only, fp16
__device__ __half g_q[(size_t)NH * LSEQ * HD];       // pre-scaled by D^-0.5
__device__ __half g_k[(size_t)NH * LSEQ * HD];
__device__ __half g_v[(size_t)NH * LSEQ * HD];
__device__ __half g_cat[(size_t)LSEQ * CATN];
__device__ __half g_w1h[(size_t)HID * W1N];
__device__ __half g_w2h[(size_t)CATN * HID];

// ---------------- async-copy / mma helpers -----------------------------------
__device__ __forceinline__ void cp16(unsigned dst, const void* src) {
    asm volatile("cp.async.cg.shared.global [%0], [%1], 16;\n" :: "r"(dst), "l"(src));
}
__device__ __forceinline__ void cp_commit() {
    asm volatile("cp.async.commit_group;\n");
}
__device__ __forceinline__ void cp_wait0() {
    asm volatile("cp.async.wait_group 0;\n");
}
__device__ __forceinline__ void cp_wait1() {
    asm volatile("cp.async.wait_group 1;\n");
}
__device__ __forceinline__ unsigned saddr(const void* p) {
    return (unsigned)__cvta_generic_to_shared(p);
}
__device__ __forceinline__ void ldsm4(uint32_t& r0, uint32_t& r1, uint32_t& r2,
                                      uint32_t& r3, unsigned addr) {
    asm volatile("ldmatrix.sync.aligned.m8n8.x4.shared.b16 {%0,%1,%2,%3}, [%4];"
                 : "=r"(r0), "=r"(r1), "=r"(r2), "=r"(r3) : "r"(addr));
}
__device__ __forceinline__ void ldsm4t(uint32_t& r0, uint32_t& r1, uint32_t& r2,
                                       uint32_t& r3, unsigned addr) {
    asm volatile("ldmatrix.sync.aligned.m8n8.x4.trans.shared.b16 {%0,%1,%2,%3}, [%4];"
                 : "=r"(r0), "=r"(r1), "=r"(r2), "=r"(r3) : "r"(addr));
}
__device__ __forceinline__ void mma16816(float* d, const uint32_t* a,
                                         uint32_t b0, uint32_t b1) {
    asm volatile(
        "mma.sync.aligned.m16n8k16.row.col.f32.f16.f16.f32 "
        "{%0,%1,%2,%3}, {%4,%5,%6,%7}, {%8,%9}, {%0,%1,%2,%3};\n"
        : "+f"(d[0]), "+f"(d[1]), "+f"(d[2]), "+f"(d[3])
        : "r"(a[0]), "r"(a[1]), "r"(a[2]), "r"(a[3]), "r"(b0), "r"(b1));
}
__device__ __forceinline__ uint32_t packh2(float x, float y) {
    __half2 h = __floats2half2_rn(x, y);
    return *reinterpret_cast<uint32_t*>(&h);
}

// ---------------- 0) fp32 -> fp16 weight conversion --------------------------
__global__ void k_convert_h(const float* __restrict__ in, __half* __restrict__ out,
                            size_t n8) {
    const float4* in4 = reinterpret_cast<const float4*>(in);
    uint4* out4 = reinterpret_cast<uint4*>(out);
    for (size_t i = (size_t)blockIdx.x * 256 + threadIdx.x; i < n8;
         i += (size_t)gridDim.x * 256) {
        float4 a = in4[2 * i], b = in4[2 * i + 1];
        __half2 h0 = __floats2half2_rn(a.x, a.y);
        __half2 h1 = __floats2half2_rn(a.z, a.w);
        __half2 h2 = __floats2half2_rn(b.x, b.y);
        __half2 h3 = __floats2half2_rn(b.z, b.w);
        uint4 o;
        o.x = *reinterpret_cast<unsigned*>(&h0);
        o.y = *reinterpret_cast<unsigned*>(&h1);
        o.z = *reinterpret_cast<unsigned*>(&h2);
        o.w = *reinterpret_cast<unsigned*>(&h3);
        out4[i] = o;
    }
}

// ---------------- 1) mod = silu(vec) @ mod_w + mod_b ------------------------
__global__ void k_mod_gemv(const float* __restrict__ vec,
                           const float* __restrict__ mw,
                           const float* __restrict__ mb) {
    __shared__ float sv[HID];
    int tid = threadIdx.x;
    for (int i = tid; i < HID; i += 256) {
        float v = vec[i];
        sv[i] = v / (1.f + expf(-v));
    }
    __syncthreads();
    int j = tid & 63, ky = tid >> 6;
    int col = blockIdx.x * 64 + j;
    const float* wp = mw + col;
    float acc = 0.f;
    int i0 = ky * 768;
#pragma unroll 4
    for (int i = i0; i < i0 + 768; ++i)
        acc += sv[i] * wp[(size_t)i * (3 * HID)];
    __shared__ float red[4][64];
    red[ky][j] = acc;
    __syncthreads();
    if (ky == 0)
        g_mod[col] = red[0][j] + red[1][j] + red[2][j] + red[3][j] + mb[col];
}

// ---------------- 2) LayerNorm + modulate (writes fp16) ----------------------
__global__ void k_ln_mod(const float* __restrict__ x,
                         const float* __restrict__ gamma,
                         const float* __restrict__ beta) {
    int l = blockIdx.x;
    const float* xr = x + (size_t)l * HID;
    float s = 0.f, ss = 0.f;
    for (int c = threadIdx.x; c < HID; c += 256) {
        float v = xr[c];
        s += v; ss += v * v;
    }
    __shared__ float rs[8], rss[8];
    for (int o = 16; o > 0; o >>= 1) {
        s  += __shfl_xor_sync(~0u, s, o);
        ss += __shfl_xor_sync(~0u, ss, o);
    }
    int w = threadIdx.x >> 5;
    if ((threadIdx.x & 31) == 0) { rs[w] = s; rss[w] = ss; }
    __syncthreads();
    float S = 0.f, SS = 0.f;
#pragma unroll
    for (int i = 0; i < 8; ++i) { S += rs[i]; SS += rss[i]; }
    float mu   = S * (1.f / HID);
    float var  = SS * (1.f / HID) - mu * mu;
    float rstd = rsqrtf(var + 1e-6f);
    __half* o = g_xmod + (size_t)l * HID;
    for (int c = threadIdx.x; c < HID; c += 256) {
        float ln = (xr[c] - mu) * rstd * gamma[c] + beta[c];
        o[c] = __float2half_rn((1.f + g_mod[HID + c]) * ln + g_mod[c]);
    }
}

// ---------------- FP16 GEMM: raw mma + ldmatrix, 128x128 CTA, BK=32, 3-stage -
// 8 warps (4 along M x 2 along N), warp tile 32x64. Direct register epilogue.
#define BM 128
#define BN 128
#define BK 32
#define NSTG 3
#define AS_H 40
#define BS_H 136
#define STG_A (BM * AS_H)
#define STG_B (BK * BS_H)
#define GEMM_DSMEM (NSTG * (STG_A + STG_B) * 2)

__global__ void __launch_bounds__(256, 2) k_gemm(
    const __half* __restrict__ A, int lda,
    const __half* __restrict__ B, int ldb, int K,
    const float* __restrict__ bias, int mode,
    float* __restrict__ f_out,
    const float* __restrict__ gate,
    const float* __restrict__ resid) {
    extern __shared__ __half hsm[];

    int tid = threadIdx.x;
    int m0 = blockIdx.x * BM, n0 = blockIdx.y * BN;
    int w = tid >> 5, lane = tid & 31;
    int wm = w & 3, wn = w >> 2;   // warp tile 32x64

    int ar = tid >> 1, ac = (tid & 1) * 16;   // A copy: 2 thr/row, 16 halves
    int br = tid >> 3, bc = (tid & 7) * 16;   // B copy: 8 thr/row, 16 halves

    int lm = lane >> 3, lr = lane & 7;        // ldmatrix lane mapping
    int fr = lane >> 2, fc = (lane & 3) * 2;  // mma acc lane mapping

    // acc[i][c][4]: i = m half (16 rows), c = n8 chunk (8 chunks of 8 cols)
    float acc[2][8][4];
#pragma unroll
    for (int i = 0; i < 2; ++i)
#pragma unroll
        for (int c = 0; c < 8; ++c)
#pragma unroll
            for (int j = 0; j < 4; ++j) acc[i][c][j] = 0.f;

    int nsteps = K / BK;
    auto issue = [&](int s) {
        int k0 = s * BK;
        __half* As = hsm + (s % NSTG) * (STG_A + STG_B);
        __half* Bs = As + STG_A;
        {
            const __half* src = A + (size_t)(m0 + ar) * lda + k0 + ac;
            unsigned dst = saddr(As + ar * AS_H + ac);
            cp16(dst, src);
            cp16(dst + 16, src + 8);
        }
        {
            const __half* src = B + (size_t)(k0 + br) * ldb + n0 + bc;
            unsigned dst = saddr(Bs + br * BS_H + bc);
            cp16(dst, src);
            cp16(dst + 16, src + 8);
        }
    };

    issue(0); cp_commit();
    issue(1); cp_commit();

    for (int s = 0; s < nsteps; ++s) {
        if (s + 1 < nsteps) cp_wait1(); else cp_wait0();
        __syncthreads();
        if (s + 2 < nsteps) { issue(s + 2); cp_commit(); }
        __half* As = hsm + (s % NSTG) * (STG_A + STG_B);
        __half* Bs = As + STG_A;
        unsigned abase = saddr(As), bbase = saddr(Bs);
#pragma unroll
        for (int kt = 0; kt < 2; ++kt) {
            int kk = kt * 16;
            // A fragments: 2 x m16k16 (rows wm*32 + i*16)
            uint32_t a[2][4];
#pragma unroll
            for (int i = 0; i < 2; ++i) {
                unsigned addr = abase +
                    ((wm * 32 + i * 16 + (lm & 1) * 8 + lr) * AS_H + kk + (lm >> 1) * 8) * 2;
                ldsm4(a[i][0], a[i][1], a[i][2], a[i][3], addr);
            }
            // B fragments: 4 x k16n16 windows (trans) -> 8 n8 chunk pairs
            uint32_t b[8][2];
#pragma unroll
            for (int bw = 0; bw < 4; ++bw) {
                unsigned addr = bbase +
                    ((kk + (lm & 1) * 8 + lr) * BS_H + wn * 64 + bw * 16 + (lm >> 1) * 8) * 2;
                uint32_t r0, r1, r2, r3;
                ldsm4t(r0, r1, r2, r3, addr);
                b[2 * bw][0] = r0; b[2 * bw][1] = r1;
                b[2 * bw + 1][0] = r2; b[2 * bw + 1][1] = r3;
            }
#pragma unroll
            for (int i = 0; i < 2; ++i)
#pragma unroll
                for (int c = 0; c < 8; ++c)
                    mma16816(acc[i][c], a[i], b[c][0], b[c][1]);
        }
    }

    // direct register epilogue: thread owns (fr, fr+8) x (fc, fc+1) per chunk
    bool isgelu = (mode == 0) && (n0 >= QKVN);
#pragma unroll
    for (int i = 0; i < 2; ++i) {
        int gm0 = m0 + wm * 32 + i * 16 + fr;
        int gm1 = gm0 + 8;
#pragma unroll
        for (int c = 0; c < 8; ++c) {
            int gn = n0 + wn * 64 + c * 8 + fc;
            float b0 = bias[gn], b1 = bias[gn + 1];
            float v00 = acc[i][c][0] + b0, v01 = acc[i][c][1] + b1;
            float v10 = acc[i][c][2] + b0, v11 = acc[i][c][3] + b1;
            if (mode == 0) {
                if (isgelu) {
                    float t, g;
                    t = 0.7978845608028654f * (v00 + 0.044715f * v00 * v00 * v00);
                    g = 0.5f * v00 * (1.f + tanhf(t)); v00 = g;
                    t = 0.7978845608028654f * (v01 + 0.044715f * v01 * v01 * v01);
                    g = 0.5f * v01 * (1.f + tanhf(t)); v01 = g;
                    t = 0.7978845608028654f * (v10 + 0.044715f * v10 * v10 * v10);
                    g = 0.5f * v10 * (1.f + tanhf(t)); v10 = g;
                    t = 0.7978845608028654f * (v11 + 0.044715f * v11 * v11 * v11);
                    g = 0.5f * v11 * (1.f + tanhf(t)); v11 = g;
                    int col = HID + (gn - QKVN);
                    *reinterpret_cast<uint32_t*>(&g_cat[(size_t)gm0 * CATN + col]) = packh2(v00, v01);
                    *reinterpret_cast<uint32_t*>(&g_cat[(size_t)gm1 * CATN + col]) = packh2(v10, v11);
                } else {
                    *reinterpret_cast<uint32_t*>(&g_h[(size_t)gm0 * QKVN + gn]) = packh2(v00, v01);
                    *reinterpret_cast<uint32_t*>(&g_h[(size_t)gm1 * QKVN + gn]) = packh2(v10, v11);
                }
            } else {
                float2 o0, o1;
                o0.x = resid[(size_t)gm0 * HID + gn]     + gate[gn]     * v00;
                o0.y = resid[(size_t)gm0 * HID + gn + 1] + gate[gn + 1] * v01;
                o1.x = resid[(size_t)gm1 * HID + gn]     + gate[gn]     * v10;
                o1.y = resid[(size_t)gm1 * HID + gn + 1] + gate[gn + 1] * v11;
                *reinterpret_cast<float2*>(&f_out[(size_t)gm0 * HID + gn]) = o0;
                *reinterpret_cast<float2*>(&f_out[(size_t)gm1 * HID + gn]) = o1;
            }
        }
    }
}

// ---------------- 3) q/k rmsnorm + rope, v copy; [H][L][D] half --------------
__global__ void k_qkv(const float* __restrict__ pe,
                      const float* __restrict__ qs,
                      const float* __restrict__ ks) {
    int l = blockIdx.x, hh = blockIdx.y, d = threadIdx.x;
    const __half* hrow = g_h + (size_t)l * QKVN;
    float qv = __half2float(hrow[hh * HD + d]);
    float kv = __half2float(hrow[HID + hh * HD + d]);
    float vv = __half2float(hrow[2 * HID + hh * HD + d]);
    float sq = qv * qv, sk = kv * kv;
    for (int o = 16; o > 0; o >>= 1) {
        sq += __shfl_xor_sync(~0u, sq, o);
        sk += __shfl_xor_sync(~0u, sk, o);
    }
    __shared__ float wsq[4], wsk[4];
    int w = d >> 5;
    if ((d & 31) == 0) { wsq[w] = sq; wsk[w] = sk; }
    __syncthreads();
    float msq = (wsq[0] + wsq[1] + wsq[2] + wsq[3]) * (1.f / HD);
    float msk = (wsk[0] + wsk[1] + wsk[2] + wsk[3]) * (1.f / HD);
    __shared__ float nq[HD], nk[HD];
    nq[d] = qv * rsqrtf(msq + 1e-6f) * qs[d];
    nk[d] = kv * rsqrtf(msk + 1e-6f) * ks[d];
    __syncthreads();
    int c = d >> 1, r = d & 1;
    const float* pp = pe + ((size_t)l * 64 + c) * 4 + r * 2;
    float qr = pp[0] * nq[2 * c] + pp[1] * nq[2 * c + 1];
    float kr = pp[0] * nk[2 * c] + pp[1] * nk[2 * c + 1];
    size_t base = ((size_t)hh * LSEQ + l) * HD + d;
    g_q[base] = __float2half_rn(qr * 0.08838834764831845f);  // * D^-0.5
    g_k[base] = __float2half_rn(kr);
    g_v[base] = __float2half_rn(vv);
}

// ---------------- 4) flash attention: 128 q rows/CTA, 8 warps ----------------
#define KS_H 136                       // halves per K/V tile row
#define FA_BUF (64 * KS_H)             // one tile buffer (halves)
#define FA_NSTG 3
#define FA_DSMEM (FA_NSTG * 2 * FA_BUF * 2)
#define NKT (LSEQ / 64)                // 32 kv tiles

__global__ void __launch_bounds__(256, 1) k_fattn() {
    extern __shared__ __half fsm[];
    int tid = threadIdx.x, w = tid >> 5, lane = tid & 31;
    int hh = blockIdx.y;
    int q0 = blockIdx.x * 128;
    const __half* Qg = g_q + ((size_t)hh * LSEQ + q0 + w * 16) * HD;
    const __half* Kg = g_k + (size_t)hh * LSEQ * HD;
    const __half* Vg = g_v + (size_t)hh * LSEQ * HD;

    int fr = lane >> 2;          // 0..7
    int fc = (lane & 3) * 2;     // 0,2,4,6
    uint32_t qa[8][4];
#pragma unroll
    for (int kc = 0; kc < 8; ++kc) {
        qa[kc][0] = *reinterpret_cast<const uint32_t*>(&Qg[(size_t)fr * HD + kc * 16 + fc]);
        qa[kc][1] = *reinterpret_cast<const uint32_t*>(&Qg[(size_t)(fr + 8) * HD + kc * 16 + fc]);
        qa[kc][2] = *reinterpret_cast<const uint32_t*>(&Qg[(size_t)fr * HD + kc * 16 + 8 + fc]);
        qa[kc][3] = *reinterpret_cast<const uint32_t*>(&Qg[(size_t)(fr + 8) * HD + kc * 16 + 8 + fc]);
    }

    float o[16][4];
#pragma unroll
    for (int c = 0; c < 16; ++c)
#pragma unroll
        for (int j = 0; j < 4; ++j) o[c][j] = 0.f;
    float m0 = -1e30f, m1 = -1e30f, l0 = 0.f, l1 = 0.f;

    int sr = tid >> 2, sc = (tid & 3) * 32;
    auto stg = [&](int t) {
        __half* Ks = fsm + (t % FA_NSTG) * 2 * FA_BUF;
        __half* Vs = Ks + FA_BUF;
        const __half* ksrc = Kg + (size_t)(t * 64 + sr) * HD + sc;
        unsigned kd = saddr(Ks + sr * KS_H + sc);
#pragma unroll
        for (int p = 0; p < 4; ++p) cp16(kd + p * 16, ksrc + p * 8);
        const __half* vsrc = Vg + (size_t)(t * 64 + sr) * HD + sc;
        unsigned vd = saddr(Vs + sr * KS_H + sc);
#pragma unroll
        for (int p = 0; p < 4; ++p) cp16(vd + p * 16, vsrc + p * 8);
    };

    stg(0); cp_commit();
    stg(1); cp_commit();

    int lm = lane >> 3, lr = lane & 7;

    for (int t = 0; t < NKT; ++t) {
        if (t + 1 < NKT) cp_wait1(); else cp_wait0();
        __syncthreads();
        if (t + 2 < NKT) { stg(t + 2); cp_commit(); }
        __half* Ks = fsm + (t % FA_NSTG) * 2 * FA_BUF;
        __half* Vs = Ks + FA_BUF;
        unsigned kbase = saddr(Ks), vbase = saddr(Vs);

        float s[8][4];
#pragma unroll
        for (int c = 0; c < 8; ++c)
#pragma unroll
            for (int j = 0; j < 4; ++j) s[c][j] = 0.f;
#pragma unroll
        for (int kc = 0; kc < 8; ++kc) {
#pragma unroll
            for (int cp = 0; cp < 4; ++cp) {
                unsigned addr = kbase +
                    (((2 * cp + (lm >> 1)) * 8 + lr) * KS_H + kc * 16 + (lm & 1) * 8) * 2;
                uint32_t b0, b1, b2, b3;
                ldsm4(b0, b1, b2, b3, addr);
                mma16816(s[2 * cp], qa[kc], b0, b1);
                mma16816(s[2 * cp + 1], qa[kc], b2, b3);
            }
        }

        float t0 = -1e30f, t1 = -1e30f;
#pragma unroll
        for (int c = 0; c < 8; ++c) {
            t0 = fmaxf(t0, fmaxf(s[c][0], s[c][1]));
            t1 = fmaxf(t1, fmaxf(s[c][2], s[c][3]));
        }
        t0 = fmaxf(t0, __shfl_xor_sync(~0u, t0, 1));
        t0 = fmaxf(t0, __shfl_xor_sync(~0u, t0, 2));
        t1 = fmaxf(t1, __shfl_xor_sync(~0u, t1, 1));
        t1 = fmaxf(t1, __shfl_xor_sync(~0u, t1, 2));
        float mn0 = fmaxf(m0, t0), mn1 = fmaxf(m1, t1);
        float sc0 = __expf(m0 - mn0), sc1 = __expf(m1 - mn1);
        m0 = mn0; m1 = mn1;
        uint32_t ph[8][2];
        float ps0 = 0.f, ps1 = 0.f;
#pragma unroll
        for (int c = 0; c < 8; ++c) {
            float e0 = __expf(s[c][0] - mn0);
            float e1 = __expf(s[c][1] - mn0);
            float e2 = __expf(s[c][2] - mn1);
            float e3 = __expf(s[c][3] - mn1);
            ps0 += e0 + e1; ps1 += e2 + e3;
            ph[c][0] = packh2(e0, e1);
            ph[c][1] = packh2(e2, e3);
        }
        l0 = l0 * sc0 + ps0;
        l1 = l1 * sc1 + ps1;
#pragma unroll
        for (int c = 0; c < 16; ++c) {
            o[c][0] *= sc0; o[c][1] *= sc0;
            o[c][2] *= sc1; o[c][3] *= sc1;
        }

#pragma unroll
        for (int kg = 0; kg < 4; ++kg) {
            uint32_t pa[4] = {ph[2 * kg][0], ph[2 * kg][1],
                              ph[2 * kg + 1][0], ph[2 * kg + 1][1]};
#pragma unroll
            for (int cp = 0; cp < 8; ++cp) {
                unsigned addr = vbase +
                    ((kg * 16 + (lm & 1) * 8 + lr) * KS_H + (2 * cp + (lm >> 1)) * 8) * 2;
                uint32_t b0, b1, b2, b3;
                ldsm4t(b0, b1, b2, b3, addr);
                mma16816(o[2 * cp], pa, b0, b1);
                mma16816(o[2 * cp + 1], pa, b2, b3);
            }
        }
    }

    l0 += __shfl_xor_sync(~0u, l0, 1);
    l0 += __shfl_xor_sync(~0u, l0, 2);
    l1 += __shfl_xor_sync(~0u, l1, 1);
    l1 += __shfl_xor_sync(~0u, l1, 2);
    float il0 = 1.f / l0, il1 = 1.f / l1;
    int row0 = q0 + w * 16 + fr;
    int row1 = row0 + 8;
#pragma unroll
    for (int c = 0; c < 16; ++c) {
        int col = hh * HD + c * 8 + fc;
        *reinterpret_cast<uint32_t*>(&g_cat[(size_t)row0 * CATN + col]) =
            packh2(o[c][0] * il0, o[c][1] * il0);
        *reinterpret_cast<uint32_t*>(&g_cat[(size_t)row1 * CATN + col]) =
            packh2(o[c][2] * il1, o[c][3] * il1);
    }
}

// ---------------- launch -----------------------------------------------------
extern "C" void kernel_launch(void* const* d_in, const int* in_sizes, int n_in,
                              void* d_out, int out_size) {
    const float* x     = (const float*)d_in[0];
    const float* vec   = (const float*)d_in[1];
    const float* pe    = (const float*)d_in[2];
    const float* mod_w = (const float*)d_in[3];
    const float* mod_b = (const float*)d_in[4];
    const float* ln_g  = (const float*)d_in[5];
    const float* ln_b  = (const float*)d_in[6];
    const float* w1    = (const float*)d_in[7];
    const float* b1    = (const float*)d_in[8];
    const float* q_s   = (const float*)d_in[9];
    const float* k_s   = (const float*)d_in[10];
    const float* w2    = (const float*)d_in[11];
    const float* b2    = (const float*)d_in[12];
    float* out = (float*)d_out;

    __half *p_xmod, *p_cat, *p_w1h, *p_w2h;
    float *p_mod;
    cudaGetSymbolAddress((void**)&p_xmod, g_xmod);
    cudaGetSymbolAddress((void**)&p_cat,  g_cat);
    cudaGetSymbolAddress((void**)&p_mod,  g_mod);
    cudaGetSymbolAddress((void**)&p_w1h,  g_w1h);
    cudaGetSymbolAddress((void**)&p_w2h,  g_w2h);

    cudaFuncSetAttribute(k_fattn, cudaFuncAttributeMaxDynamicSharedMemorySize,
                         FA_DSMEM);
    cudaFuncSetAttribute(k_gemm, cudaFuncAttributeMaxDynamicSharedMemorySize,
                         GEMM_DSMEM);

    k_mod_gemv<<<144, 256>>>(vec, mod_w, mod_b);                       // 1
    k_convert_h<<<4096, 256>>>(w1, p_w1h, (size_t)HID * W1N / 8);      // 2
    k_ln_mod<<<LSEQ, 256>>>(x, ln_g, ln_b);                            // 3
    // h|gelu(mlp) = x_mod @ w1 + b1       (launch #4 -> profiled)
    k_gemm<<<dim3(16, 168), 256, GEMM_DSMEM>>>(p_xmod, HID, p_w1h, W1N,
                                               HID, b1, 0,
                                               nullptr, nullptr, nullptr);
    k_qkv<<<dim3(LSEQ, NH), 128>>>(pe, q_s, k_s);                      // 5
    k_fattn<<<dim3(LSEQ / 128, NH), 256, FA_DSMEM>>>();                // 6
    k_convert_h<<<4096, 256>>>(w2, p_w2h, (size_t)CATN * HID / 8);     // 7
    // out = x + gate * (cat @ w2 + b2)
    k_gemm<<<dim3(16, 24), 256, GEMM_DSMEM>>>(p_cat, CATN, p_w2h, HID,
                                              CATN, b2, 1,
                                              out, p_mod + 2 * HID, x);
    (void)in_sizes; (void)n_in; (void)out_size;
}